// round 1
// baseline (speedup 1.0000x reference)
#include <cuda_runtime.h>
#include <cuda_bf16.h>
#include <math.h>

// Problem constants
#define BX   4
#define TT   1024
#define SS   1024
#define EE   1024
#define HH   16
#define DH   64

// Scratch (device globals; no allocation allowed)
__device__ float g_Q[BX * HH * TT * DH];   // [B,H,T,D]
__device__ float g_K[BX * HH * SS * DH];   // [B,H,S,D]
__device__ float g_V[BX * HH * SS * DH];   // [B,H,S,D]
__device__ float g_P[TT * BX * EE];        // [T,B,E] pre-projection

// ---------------------------------------------------------------------------
// GEMM: C = A[M,1024] * W[1024,1024] (+bias). Tile 128x64, K-tile 16,
// 256 threads, 8x4 micro-tile per thread.
// mode 0: C[m*1024+n] = acc + bias[n]
// mode 1: scatter to [B,H,L,D]: b=m/L, l=m%L, h=n/64, d=n%64
// ---------------------------------------------------------------------------
#define GBM 128
#define GBN 64
#define GBK 16

__global__ __launch_bounds__(256)
void gemm_kernel(const float* __restrict__ A, const float* __restrict__ W,
                 const float* __restrict__ bias, float* __restrict__ C,
                 int mode, int L)
{
    __shared__ float As[GBM][GBK + 1];   // pad to kill row-broadcast conflicts
    __shared__ float Ws[GBK][GBN];

    const int tid = threadIdx.x;
    const int m0 = blockIdx.y * GBM;
    const int n0 = blockIdx.x * GBN;
    const int i = tid >> 4;   // 0..15 -> rows i*8 .. i*8+7
    const int j = tid & 15;   // cols j + 16*v, v=0..3

    float acc[8][4];
#pragma unroll
    for (int u = 0; u < 8; u++)
#pragma unroll
        for (int v = 0; v < 4; v++) acc[u][v] = 0.f;

    for (int k0 = 0; k0 < 1024; k0 += GBK) {
        // Load A tile: 128x16
#pragma unroll
        for (int t = 0; t < 8; t++) {
            int idx = tid + t * 256;
            int mm = idx >> 4, kk = idx & 15;
            As[mm][kk] = A[(size_t)(m0 + mm) * 1024 + k0 + kk];
        }
        // Load W tile: 16x64
#pragma unroll
        for (int t = 0; t < 4; t++) {
            int idx = tid + t * 256;
            int kk = idx >> 6, nn = idx & 63;
            Ws[kk][nn] = W[(size_t)(k0 + kk) * 1024 + n0 + nn];
        }
        __syncthreads();

#pragma unroll
        for (int kk = 0; kk < GBK; kk++) {
            float a[8], b[4];
#pragma unroll
            for (int u = 0; u < 8; u++) a[u] = As[i * 8 + u][kk];
#pragma unroll
            for (int v = 0; v < 4; v++) b[v] = Ws[kk][j + 16 * v];
#pragma unroll
            for (int u = 0; u < 8; u++)
#pragma unroll
                for (int v = 0; v < 4; v++) acc[u][v] = fmaf(a[u], b[v], acc[u][v]);
        }
        __syncthreads();
    }

#pragma unroll
    for (int u = 0; u < 8; u++) {
        int m = m0 + i * 8 + u;
#pragma unroll
        for (int v = 0; v < 4; v++) {
            int n = n0 + j + 16 * v;
            float val = acc[u][v];
            if (mode == 0) {
                C[(size_t)m * 1024 + n] = val + bias[n];
            } else {
                int b  = m / L, l = m % L;
                int h  = n >> 6, d = n & 63;
                C[(((size_t)(b * HH + h) * L + l) * DH) + d] = val;
            }
        }
    }
}

// ---------------------------------------------------------------------------
// Attention: one block handles (b,h) and 32 t-rows.
// SMEM: scores [32][1032] + q [32][65] + kv tile [128][65]  (~170 KB dynamic)
// Phase 1: scores = q*K^T/sqrt(D) + additive mask  -> smem
// Phase 2: softmax (8 threads per row), optionally write attn to gmem
// Phase 3: O = P @ V -> g_P at [t, b, h*64 + d]
// ---------------------------------------------------------------------------
#define AT 32
#define CT 128
#define SPITCH 1032   // 1024 + 8 (bank-conflict-free softmax)
#define KPITCH 65

__global__ __launch_bounds__(256)
void attn_kernel(const float* __restrict__ Q, const float* __restrict__ K,
                 const float* __restrict__ V,
                 const float* __restrict__ tpad, const float* __restrict__ spad,
                 const float* __restrict__ amask, const int* __restrict__ causal_p,
                 float* __restrict__ attn_out, float* __restrict__ P)
{
    extern __shared__ float sm[];
    float* s_s  = sm;                        // [32][SPITCH]
    float* s_q  = sm + AT * SPITCH;          // [32][KPITCH]
    float* s_kv = s_q + AT * KPITCH;         // [128][KPITCH]

    const int tid = threadIdx.x;
    const int bh  = blockIdx.y;
    const int b   = bh >> 4;
    const int h   = bh & 15;
    const int t0  = blockIdx.x * AT;
    const bool causal = (causal_p[0] != 0);   // works for int32(1) or f32(1.0) bits

    const size_t qbase = ((size_t)bh * TT + t0) * DH;
    const size_t kbase = (size_t)bh * SS * DH;

    // Load q rows, pre-scaled by 1/sqrt(64)
    for (int idx = tid; idx < AT * DH; idx += 256) {
        int r = idx >> 6, d = idx & 63;
        s_q[r * KPITCH + d] = Q[qbase + (size_t)r * DH + d] * 0.125f;
    }

    const int i = tid >> 5;   // 0..7 -> rows i*4 .. i*4+3
    const int j = tid & 31;   // cols j + 32*v

    // ---------------- Phase 1: scores ----------------
    for (int c0 = 0; c0 < SS; c0 += CT) {
        __syncthreads();
        // load K tile [128][64] via float4
        for (int idx = tid; idx < CT * 16; idx += 256) {
            int r = idx >> 4, d4 = idx & 15;
            float4 kv = *(const float4*)&K[kbase + (size_t)(c0 + r) * DH + d4 * 4];
            float* p = &s_kv[r * KPITCH + d4 * 4];
            p[0] = kv.x; p[1] = kv.y; p[2] = kv.z; p[3] = kv.w;
        }
        __syncthreads();

        float acc[4][4];
#pragma unroll
        for (int u = 0; u < 4; u++)
#pragma unroll
            for (int v = 0; v < 4; v++) acc[u][v] = 0.f;

#pragma unroll 16
        for (int d = 0; d < DH; d++) {
            float a[4], kx[4];
#pragma unroll
            for (int u = 0; u < 4; u++) a[u] = s_q[(i * 4 + u) * KPITCH + d];
#pragma unroll
            for (int v = 0; v < 4; v++) kx[v] = s_kv[(j + 32 * v) * KPITCH + d];
#pragma unroll
            for (int u = 0; u < 4; u++)
#pragma unroll
                for (int v = 0; v < 4; v++) acc[u][v] = fmaf(a[u], kx[v], acc[u][v]);
        }

        // additive mask (NOT -inf masking: faithful to reference) + store scores
#pragma unroll
        for (int u = 0; u < 4; u++) {
            int t = t0 + i * 4 + u;
            float tm = tpad[b * TT + t];
#pragma unroll
            for (int v = 0; v < 4; v++) {
                int s = c0 + j + 32 * v;
                float m = tm * spad[b * SS + s] * amask[((size_t)b * TT + t) * SS + s];
                if (causal && s > t) m = 0.f;
                s_s[(i * 4 + u) * SPITCH + s] = acc[u][v] + m;
            }
        }
    }
    __syncthreads();

    // ---------------- Phase 2: softmax (8 threads / row) ----------------
    {
        const int r    = tid >> 3;
        const int lane = tid & 7;
        float* row = s_s + r * SPITCH;

        float mx = -1e30f;
        for (int c = lane; c < SS; c += 8) mx = fmaxf(mx, row[c]);
#pragma unroll
        for (int o = 4; o > 0; o >>= 1) mx = fmaxf(mx, __shfl_xor_sync(0xffffffffu, mx, o, 8));

        float sum = 0.f;
        for (int c = lane; c < SS; c += 8) {
            float e = __expf(row[c] - mx);
            row[c] = e;
            sum += e;
        }
#pragma unroll
        for (int o = 4; o > 0; o >>= 1) sum += __shfl_xor_sync(0xffffffffu, sum, o, 8);

        float inv = 1.f / sum;
        size_t abase = ((size_t)bh * TT + (t0 + r)) * SS;
        for (int c = lane; c < SS; c += 8) {
            float p = row[c] * inv;
            row[c] = p;
            if (attn_out) attn_out[abase + c] = p;
        }
    }
    __syncthreads();

    // ---------------- Phase 3: O = P @ V ----------------
    float oacc[4][2];
#pragma unroll
    for (int u = 0; u < 4; u++) { oacc[u][0] = 0.f; oacc[u][1] = 0.f; }

    for (int c0 = 0; c0 < SS; c0 += CT) {
        __syncthreads();
        for (int idx = tid; idx < CT * 16; idx += 256) {
            int r = idx >> 4, d4 = idx & 15;
            float4 vv = *(const float4*)&V[kbase + (size_t)(c0 + r) * DH + d4 * 4];
            float* p = &s_kv[r * KPITCH + d4 * 4];
            p[0] = vv.x; p[1] = vv.y; p[2] = vv.z; p[3] = vv.w;
        }
        __syncthreads();

#pragma unroll 8
        for (int jj = 0; jj < CT; jj++) {
            float bv0 = s_kv[jj * KPITCH + j];
            float bv1 = s_kv[jj * KPITCH + j + 32];
#pragma unroll
            for (int u = 0; u < 4; u++) {
                float a = s_s[(i * 4 + u) * SPITCH + c0 + jj];
                oacc[u][0] = fmaf(a, bv0, oacc[u][0]);
                oacc[u][1] = fmaf(a, bv1, oacc[u][1]);
            }
        }
    }

    // write O into pre-projection buffer: P[t, b, h*64 + d]
#pragma unroll
    for (int u = 0; u < 4; u++) {
        int t = t0 + i * 4 + u;
        size_t pb = ((size_t)t * BX + b) * EE + h * DH;
        P[pb + j]      = oacc[u][0];
        P[pb + j + 32] = oacc[u][1];
    }
}

// ---------------------------------------------------------------------------
// Launch
// ---------------------------------------------------------------------------
extern "C" void kernel_launch(void* const* d_in, const int* in_sizes, int n_in,
                              void* d_out, int out_size)
{
    const float* src   = (const float*)d_in[0];   // [B,S,E]
    const float* tgt   = (const float*)d_in[1];   // [B,T,E]
    const float* spad  = (const float*)d_in[2];   // [B,S]
    const float* tpad  = (const float*)d_in[3];   // [B,T]
    const float* amask = (const float*)d_in[4];   // [B,T,S]
    const int*   caus  = (const int*)  d_in[5];   // scalar
    const float* Wq    = (const float*)d_in[6];
    const float* Wk    = (const float*)d_in[7];
    const float* Wv    = (const float*)d_in[8];
    const float* Wo    = (const float*)d_in[9];
    const float* bo    = (const float*)d_in[10];

    const size_t OUT_N  = (size_t)TT * BX * EE;        // 4,194,304
    const size_t ATTN_N = (size_t)BX * HH * TT * SS;   // 67,108,864

    float* out_p  = nullptr;
    float* attn_p = nullptr;
    if ((size_t)out_size == OUT_N + ATTN_N) {
        out_p  = (float*)d_out;
        attn_p = (float*)d_out + OUT_N;
    } else if ((size_t)out_size == ATTN_N) {
        attn_p = (float*)d_out;
    } else {
        out_p  = (float*)d_out;
    }

    float *Qp, *Kp, *Vp, *Pp;
    cudaGetSymbolAddress((void**)&Qp, g_Q);
    cudaGetSymbolAddress((void**)&Kp, g_K);
    cudaGetSymbolAddress((void**)&Vp, g_V);
    cudaGetSymbolAddress((void**)&Pp, g_P);

    // Dynamic smem for attention kernel
    const int ATTN_SMEM = (AT * SPITCH + AT * KPITCH + CT * KPITCH) * (int)sizeof(float);
    cudaFuncSetAttribute(attn_kernel, cudaFuncAttributeMaxDynamicSharedMemorySize, ATTN_SMEM);

    dim3 ggrid(EE / GBN, (BX * TT) / GBM);   // (16, 32)
    dim3 gblk(256);

    // QKV projections (mode 1 = scatter to [B,H,L,D])
    gemm_kernel<<<ggrid, gblk>>>(tgt, Wq, nullptr, Qp, 1, TT);
    gemm_kernel<<<ggrid, gblk>>>(src, Wk, nullptr, Kp, 1, SS);
    gemm_kernel<<<ggrid, gblk>>>(src, Wv, nullptr, Vp, 1, SS);

    // Attention
    dim3 agrid(TT / AT, BX * HH);  // (32, 64)
    attn_kernel<<<agrid, dim3(256), ATTN_SMEM>>>(Qp, Kp, Vp, tpad, spad, amask,
                                                 caus, attn_p, Pp);

    // Output projection: out[t,b,:] = P[t,b,:] @ Wo + bo
    if (out_p) {
        gemm_kernel<<<ggrid, gblk>>>(Pp, Wo, bo, out_p, 0, TT);
    }
}

// round 3
// speedup vs baseline: 1.3764x; 1.3764x over previous
#include <cuda_runtime.h>
#include <cuda_bf16.h>
#include <math.h>
#include <cstdint>

// Problem constants
#define BX   4
#define TT   1024
#define SS   1024
#define EE   1024
#define HH   16
#define DH   64

// Scratch (device globals; no allocation allowed)
__device__ float g_Q[BX * HH * TT * DH];   // [B,H,T,D]
__device__ float g_K[BX * HH * SS * DH];   // [B,H,S,D]
__device__ float g_V[BX * HH * SS * DH];   // [B,H,S,D]
__device__ float g_P[TT * BX * EE];        // [T,B,E] pre-projection
__device__ float g_Wt[4 * EE * EE];        // transposed weights [N,K], tf32-rounded

// ---------------------------------------------------------------------------
// Helpers
// ---------------------------------------------------------------------------
__device__ __forceinline__ uint32_t smem_u32(const void* p) {
    uint32_t a;
    asm("{ .reg .u64 t; cvta.to.shared.u64 t, %1; cvt.u32.u64 %0, t; }" : "=r"(a) : "l"(p));
    return a;
}
__device__ __forceinline__ float tf32r(float x) {
    uint32_t u;
    asm("cvt.rna.tf32.f32 %0, %1;" : "=r"(u) : "f"(x));
    return __uint_as_float(u);
}
#define SWZ128(off) ((off) ^ (((off) >> 3) & 0x70))

__device__ __forceinline__ void ldsm4(uint32_t* r, uint32_t addr) {
    asm volatile("ldmatrix.sync.aligned.m8n8.x4.shared.b16 {%0,%1,%2,%3}, [%4];"
                 : "=r"(r[0]), "=r"(r[1]), "=r"(r[2]), "=r"(r[3]) : "r"(addr));
}
__device__ __forceinline__ void mma_tf32(float* d, const uint32_t* a, uint32_t b0, uint32_t b1) {
    asm volatile("mma.sync.aligned.m16n8k8.row.col.f32.tf32.tf32.f32 "
                 "{%0,%1,%2,%3}, {%4,%5,%6,%7}, {%8,%9}, {%0,%1,%2,%3};"
                 : "+f"(d[0]), "+f"(d[1]), "+f"(d[2]), "+f"(d[3])
                 : "r"(a[0]), "r"(a[1]), "r"(a[2]), "r"(a[3]), "r"(b0), "r"(b1));
}

// ---------------------------------------------------------------------------
// Weight transpose + tf32 rounding: Wt[n,k] = tf32(W[k,n])
// ---------------------------------------------------------------------------
__global__ __launch_bounds__(256)
void transpose_tf32_kernel(const float* __restrict__ W, float* __restrict__ Wt)
{
    __shared__ float tile[32][33];
    const int k0 = blockIdx.y * 32, n0 = blockIdx.x * 32;
    const int tx = threadIdx.x & 31, ty = threadIdx.x >> 5;
#pragma unroll
    for (int t = 0; t < 4; t++)
        tile[ty + 8 * t][tx] = W[(size_t)(k0 + ty + 8 * t) * EE + n0 + tx];
    __syncthreads();
#pragma unroll
    for (int t = 0; t < 4; t++)
        Wt[(size_t)(n0 + ty + 8 * t) * EE + k0 + tx] = tf32r(tile[tx][ty + 8 * t]);
}

// ---------------------------------------------------------------------------
// tf32 mma.sync GEMM: C[4096,1024] = A[4096,1024] @ Wt[1024(N),1024(K)]^T
// Block 128x128, K-tile 32, double-buffered swizzled smem, 8 warps (4m x 2n),
// warp tile 32x64 -> 2 m16 x 8 n8 mma tiles.
// mode 0: C[m*1024+n] = acc + bias[n];  mode 1: scatter to [B,H,L,D]
// ---------------------------------------------------------------------------
#define GA0   0
#define GA1   16384
#define GB0   32768
#define GB1   49152
#define GSMEM (65536 + 1024)

__global__ __launch_bounds__(256)
void gemm_mma_kernel(const float* __restrict__ A, const float* __restrict__ Bt,
                     const float* __restrict__ bias, float* __restrict__ C,
                     int mode, int L)
{
    extern __shared__ char dyn_sm[];
    char* sm = (char*)(((uintptr_t)dyn_sm + 1023) & ~(uintptr_t)1023);
    const uint32_t sb = smem_u32(sm);

    const int tid  = threadIdx.x;
    const int wid  = tid >> 5;
    const int lane = tid & 31;
    const int wm   = wid & 3;    // 0..3 -> 32 rows each
    const int wn   = wid >> 2;   // 0..1 -> 64 cols each
    const int m0 = blockIdx.y * 128;
    const int n0 = blockIdx.x * 128;

    const float* Ap = A  + (size_t)m0 * 1024;
    const float* Bp = Bt + (size_t)n0 * 1024;

    // ldmatrix per-thread row bases (generic formula valid for A and B):
    // row = tile_base + ((lane>>3)&1)*8 + (lane&7); kchunk16 = lane>>4
    const int lrow  = ((lane >> 3) & 1) * 8 + (lane & 7);
    const int klane = lane >> 4;   // 0/1

    uint32_t aoff[2], asw[2], boff[4], bsw[4];
#pragma unroll
    for (int mt = 0; mt < 2; mt++) {
        int r = wm * 32 + mt * 16 + lrow;
        aoff[mt] = (uint32_t)r * 128;
        asw[mt]  = (uint32_t)(r & 7);
    }
#pragma unroll
    for (int nt = 0; nt < 4; nt++) {
        int r = wn * 64 + nt * 16 + lrow;
        boff[nt] = (uint32_t)r * 128;
        bsw[nt]  = (uint32_t)(r & 7);
    }

    float acc[2][8][4];
#pragma unroll
    for (int mt = 0; mt < 2; mt++)
#pragma unroll
        for (int nt = 0; nt < 8; nt++)
#pragma unroll
            for (int c = 0; c < 4; c++) acc[mt][nt][c] = 0.f;

    // load K-tile kt into buffer buf (A tf32-rounded; Bt pre-rounded)
    auto load_tile = [&](int buf, int kt) {
        const int k0 = kt * 32;
        const uint32_t ao = buf ? GA1 : GA0;
        const uint32_t bo = buf ? GB1 : GB0;
#pragma unroll
        for (int t = 0; t < 4; t++) {
            int idx = tid + t * 256;
            int r = idx >> 3, c4 = idx & 7;
            uint32_t sw = SWZ128((uint32_t)(r * 128 + c4 * 16));
            float4 va = *(const float4*)(Ap + (size_t)r * 1024 + k0 + c4 * 4);
            float4 wa;
            wa.x = tf32r(va.x); wa.y = tf32r(va.y); wa.z = tf32r(va.z); wa.w = tf32r(va.w);
            *(float4*)(sm + ao + sw) = wa;
            *(float4*)(sm + bo + sw) = *(const float4*)(Bp + (size_t)r * 1024 + k0 + c4 * 4);
        }
    };

    auto compute = [&](int buf) {
        const uint32_t ab = sb + (buf ? GA1 : GA0);
        const uint32_t bb = sb + (buf ? GB1 : GB0);
#pragma unroll
        for (int k8 = 0; k8 < 4; k8++) {
            const uint32_t kc = (uint32_t)(k8 * 2 + klane);
            uint32_t af[2][4], bf[4][4];
#pragma unroll
            for (int mt = 0; mt < 2; mt++)
                ldsm4(af[mt], ab + aoff[mt] + ((kc ^ asw[mt]) << 4));
#pragma unroll
            for (int nt = 0; nt < 4; nt++)
                ldsm4(bf[nt], bb + boff[nt] + ((kc ^ bsw[nt]) << 4));
#pragma unroll
            for (int mt = 0; mt < 2; mt++)
#pragma unroll
                for (int n8 = 0; n8 < 8; n8++) {
                    int bt = n8 >> 1, sub = n8 & 1;
                    mma_tf32(acc[mt][n8], af[mt], bf[bt][sub], bf[bt][sub + 2]);
                }
        }
    };

    load_tile(0, 0);
    __syncthreads();

#pragma unroll 1
    for (int kt = 0; kt < 32; kt++) {
        const int p = kt & 1;
        if (kt < 31) load_tile(1 - p, kt + 1);
        compute(p);
        __syncthreads();
    }

    // Epilogue: registers -> gmem (float2 stores)
    const int rbase = lane >> 2;
    const int cbase = 2 * (lane & 3);
#pragma unroll
    for (int mt = 0; mt < 2; mt++) {
#pragma unroll
        for (int nt = 0; nt < 8; nt++) {
            int n = n0 + wn * 64 + nt * 8 + cbase;
#pragma unroll
            for (int half = 0; half < 2; half++) {
                int m = m0 + wm * 32 + mt * 16 + rbase + half * 8;
                float2 v;
                v.x = acc[mt][nt][half * 2 + 0];
                v.y = acc[mt][nt][half * 2 + 1];
                if (mode == 0) {
                    v.x += bias[n];
                    v.y += bias[n + 1];
                    *(float2*)&C[(size_t)m * 1024 + n] = v;
                } else {
                    int b = m / L, l = m % L;
                    size_t o = (((size_t)(b * HH + (n >> 6)) * L + l) * DH) + (n & 63);
                    *(float2*)&C[o] = v;
                }
            }
        }
    }
}

// ---------------------------------------------------------------------------
// Attention (fp32 FFMA), 512 threads, 32 t-rows per block.
// ---------------------------------------------------------------------------
#define AT 32
#define CT 128
#define SPITCH 1032
#define KPITCH 65

__global__ __launch_bounds__(512)
void attn_kernel(const float* __restrict__ Q, const float* __restrict__ K,
                 const float* __restrict__ V,
                 const float* __restrict__ tpad, const float* __restrict__ spad,
                 const float* __restrict__ amask, const int* __restrict__ causal_p,
                 float* __restrict__ attn_out, float* __restrict__ P)
{
    extern __shared__ float smf[];
    float* s_s  = smf;                       // [32][SPITCH]
    float* s_q  = smf + AT * SPITCH;         // [32][KPITCH]
    float* s_kv = s_q + AT * KPITCH;         // [128][KPITCH]

    const int tid = threadIdx.x;
    const int bh  = blockIdx.y;
    const int b   = bh >> 4;
    const int h   = bh & 15;
    const int t0  = blockIdx.x * AT;
    const bool causal = (causal_p[0] != 0);

    const size_t qbase = ((size_t)bh * TT + t0) * DH;
    const size_t kbase = (size_t)bh * SS * DH;

    for (int idx = tid; idx < AT * DH; idx += 512) {
        int r = idx >> 6, d = idx & 63;
        s_q[r * KPITCH + d] = Q[qbase + (size_t)r * DH + d] * 0.125f;
    }

    const int i = tid >> 6;   // 0..7 -> rows i*4..i*4+3
    const int j = tid & 63;   // cols j + 64*v

    // ---------------- Phase 1: scores ----------------
    for (int c0 = 0; c0 < SS; c0 += CT) {
        __syncthreads();
        for (int idx = tid; idx < CT * 16; idx += 512) {
            int r = idx >> 4, d4 = idx & 15;
            float4 kv = *(const float4*)&K[kbase + (size_t)(c0 + r) * DH + d4 * 4];
            float* p = &s_kv[r * KPITCH + d4 * 4];
            p[0] = kv.x; p[1] = kv.y; p[2] = kv.z; p[3] = kv.w;
        }
        __syncthreads();

        float acc[4][2];
#pragma unroll
        for (int u = 0; u < 4; u++) { acc[u][0] = 0.f; acc[u][1] = 0.f; }

#pragma unroll 16
        for (int d = 0; d < DH; d++) {
            float a[4], kx[2];
#pragma unroll
            for (int u = 0; u < 4; u++) a[u] = s_q[(i * 4 + u) * KPITCH + d];
            kx[0] = s_kv[j * KPITCH + d];
            kx[1] = s_kv[(j + 64) * KPITCH + d];
#pragma unroll
            for (int u = 0; u < 4; u++) {
                acc[u][0] = fmaf(a[u], kx[0], acc[u][0]);
                acc[u][1] = fmaf(a[u], kx[1], acc[u][1]);
            }
        }

#pragma unroll
        for (int u = 0; u < 4; u++) {
            int t = t0 + i * 4 + u;
            float tm = tpad[b * TT + t];
#pragma unroll
            for (int v = 0; v < 2; v++) {
                int s = c0 + j + 64 * v;
                float m = tm * spad[b * SS + s] * amask[((size_t)b * TT + t) * SS + s];
                if (causal && s > t) m = 0.f;
                s_s[(i * 4 + u) * SPITCH + s] = acc[u][v] + m;
            }
        }
    }
    __syncthreads();

    // ---------------- Phase 2: softmax (16 threads / row) ----------------
    {
        const int r    = tid >> 4;
        const int lane = tid & 15;
        float* row = s_s + r * SPITCH;

        float mx = -1e30f;
        for (int c = lane; c < SS; c += 16) mx = fmaxf(mx, row[c]);
#pragma unroll
        for (int o = 8; o > 0; o >>= 1) mx = fmaxf(mx, __shfl_xor_sync(0xffffffffu, mx, o, 16));

        float sum = 0.f;
        for (int c = lane; c < SS; c += 16) {
            float e = __expf(row[c] - mx);
            row[c] = e;
            sum += e;
        }
#pragma unroll
        for (int o = 8; o > 0; o >>= 1) sum += __shfl_xor_sync(0xffffffffu, sum, o, 16);

        float inv = 1.f / sum;
        size_t abase = ((size_t)bh * TT + (t0 + r)) * SS;
        for (int c = lane; c < SS; c += 16) {
            float p = row[c] * inv;
            row[c] = p;
            if (attn_out) attn_out[abase + c] = p;
        }
    }
    __syncthreads();

    // ---------------- Phase 3: O = P @ V ----------------
    float oacc[4];
#pragma unroll
    for (int u = 0; u < 4; u++) oacc[u] = 0.f;

    for (int c0 = 0; c0 < SS; c0 += CT) {
        __syncthreads();
        for (int idx = tid; idx < CT * 16; idx += 512) {
            int r = idx >> 4, d4 = idx & 15;
            float4 vv = *(const float4*)&V[kbase + (size_t)(c0 + r) * DH + d4 * 4];
            float* p = &s_kv[r * KPITCH + d4 * 4];
            p[0] = vv.x; p[1] = vv.y; p[2] = vv.z; p[3] = vv.w;
        }
        __syncthreads();

#pragma unroll 8
        for (int jj = 0; jj < CT; jj++) {
            float bv = s_kv[jj * KPITCH + j];
#pragma unroll
            for (int u = 0; u < 4; u++) {
                float a = s_s[(i * 4 + u) * SPITCH + c0 + jj];
                oacc[u] = fmaf(a, bv, oacc[u]);
            }
        }
    }

#pragma unroll
    for (int u = 0; u < 4; u++) {
        int t = t0 + i * 4 + u;
        P[((size_t)t * BX + b) * EE + h * DH + j] = oacc[u];
    }
}

// ---------------------------------------------------------------------------
// Launch
// ---------------------------------------------------------------------------
extern "C" void kernel_launch(void* const* d_in, const int* in_sizes, int n_in,
                              void* d_out, int out_size)
{
    const float* src   = (const float*)d_in[0];
    const float* tgt   = (const float*)d_in[1];
    const float* spad  = (const float*)d_in[2];
    const float* tpad  = (const float*)d_in[3];
    const float* amask = (const float*)d_in[4];
    const int*   caus  = (const int*)  d_in[5];
    const float* Wq    = (const float*)d_in[6];
    const float* Wk    = (const float*)d_in[7];
    const float* Wv    = (const float*)d_in[8];
    const float* Wo    = (const float*)d_in[9];
    const float* bo    = (const float*)d_in[10];

    const size_t OUT_N  = (size_t)TT * BX * EE;
    const size_t ATTN_N = (size_t)BX * HH * TT * SS;

    float* out_p  = nullptr;
    float* attn_p = nullptr;
    if ((size_t)out_size == OUT_N + ATTN_N) {
        out_p  = (float*)d_out;
        attn_p = (float*)d_out + OUT_N;
    } else if ((size_t)out_size == ATTN_N) {
        attn_p = (float*)d_out;
    } else {
        out_p  = (float*)d_out;
    }

    float *Qp, *Kp, *Vp, *Pp, *Wtp;
    cudaGetSymbolAddress((void**)&Qp, g_Q);
    cudaGetSymbolAddress((void**)&Kp, g_K);
    cudaGetSymbolAddress((void**)&Vp, g_V);
    cudaGetSymbolAddress((void**)&Pp, g_P);
    cudaGetSymbolAddress((void**)&Wtp, g_Wt);

    const int ATTN_SMEM = (AT * SPITCH + AT * KPITCH + CT * KPITCH) * (int)sizeof(float);
    cudaFuncSetAttribute(attn_kernel, cudaFuncAttributeMaxDynamicSharedMemorySize, ATTN_SMEM);
    cudaFuncSetAttribute(gemm_mma_kernel, cudaFuncAttributeMaxDynamicSharedMemorySize, GSMEM);

    dim3 tgrid(32, 32), tblk(256);
    transpose_tf32_kernel<<<tgrid, tblk>>>(Wq, Wtp + 0 * (size_t)EE * EE);
    transpose_tf32_kernel<<<tgrid, tblk>>>(Wk, Wtp + 1 * (size_t)EE * EE);
    transpose_tf32_kernel<<<tgrid, tblk>>>(Wv, Wtp + 2 * (size_t)EE * EE);
    transpose_tf32_kernel<<<tgrid, tblk>>>(Wo, Wtp + 3 * (size_t)EE * EE);

    dim3 ggrid(8, 32), gblk(256);
    gemm_mma_kernel<<<ggrid, gblk, GSMEM>>>(tgt, Wtp + 0 * (size_t)EE * EE, nullptr, Qp, 1, TT);
    gemm_mma_kernel<<<ggrid, gblk, GSMEM>>>(src, Wtp + 1 * (size_t)EE * EE, nullptr, Kp, 1, SS);
    gemm_mma_kernel<<<ggrid, gblk, GSMEM>>>(src, Wtp + 2 * (size_t)EE * EE, nullptr, Vp, 1, SS);

    dim3 agrid(TT / AT, BX * HH);
    attn_kernel<<<agrid, dim3(512), ATTN_SMEM>>>(Qp, Kp, Vp, tpad, spad, amask,
                                                 caus, attn_p, Pp);

    if (out_p) {
        gemm_mma_kernel<<<ggrid, gblk, GSMEM>>>(Pp, Wtp + 3 * (size_t)EE * EE, bo, out_p, 0, TT);
    }
}

// round 4
// speedup vs baseline: 2.7712x; 2.0134x over previous
#include <cuda_runtime.h>
#include <cuda_bf16.h>
#include <math.h>
#include <cstdint>

// Problem constants
#define BX   4
#define TT   1024
#define SS   1024
#define EE   1024
#define HH   16
#define DH   64

// Scratch (device globals; no allocation allowed)
__device__ float g_Q[BX * HH * TT * DH];   // [B,H,T,D]
__device__ float g_K[BX * HH * SS * DH];   // [B,H,S,D]
__device__ float g_Vt[BX * HH * DH * SS];  // [B,H,D,S]  (transposed V)
__device__ float g_P[TT * BX * EE];        // [T,B,E] pre-projection
__device__ float g_Wt[4 * EE * EE];        // transposed weights [N,K], tf32-rounded

// ---------------------------------------------------------------------------
// Helpers
// ---------------------------------------------------------------------------
__device__ __forceinline__ uint32_t smem_u32(const void* p) {
    uint32_t a;
    asm("{ .reg .u64 t; cvta.to.shared.u64 t, %1; cvt.u32.u64 %0, t; }" : "=r"(a) : "l"(p));
    return a;
}
__device__ __forceinline__ float tf32r(float x) {
    uint32_t u;
    asm("cvt.rna.tf32.f32 %0, %1;" : "=r"(u) : "f"(x));
    return __uint_as_float(u);
}
#define SWZ128(off) ((off) ^ (((off) >> 3) & 0x70))

__device__ __forceinline__ void ldsm4(uint32_t* r, uint32_t addr) {
    asm volatile("ldmatrix.sync.aligned.m8n8.x4.shared.b16 {%0,%1,%2,%3}, [%4];"
                 : "=r"(r[0]), "=r"(r[1]), "=r"(r[2]), "=r"(r[3]) : "r"(addr));
}
__device__ __forceinline__ void mma_tf32(float* d, const uint32_t* a, uint32_t b0, uint32_t b1) {
    asm volatile("mma.sync.aligned.m16n8k8.row.col.f32.tf32.tf32.f32 "
                 "{%0,%1,%2,%3}, {%4,%5,%6,%7}, {%8,%9}, {%0,%1,%2,%3};"
                 : "+f"(d[0]), "+f"(d[1]), "+f"(d[2]), "+f"(d[3])
                 : "r"(a[0]), "r"(a[1]), "r"(a[2]), "r"(a[3]), "r"(b0), "r"(b1));
}

// ---------------------------------------------------------------------------
// Weight transpose + tf32 rounding: Wt[n,k] = tf32(W[k,n])
// ---------------------------------------------------------------------------
__global__ __launch_bounds__(256)
void transpose_tf32_kernel(const float* __restrict__ W, float* __restrict__ Wt)
{
    __shared__ float tile[32][33];
    const int k0 = blockIdx.y * 32, n0 = blockIdx.x * 32;
    const int tx = threadIdx.x & 31, ty = threadIdx.x >> 5;
#pragma unroll
    for (int t = 0; t < 4; t++)
        tile[ty + 8 * t][tx] = W[(size_t)(k0 + ty + 8 * t) * EE + n0 + tx];
    __syncthreads();
#pragma unroll
    for (int t = 0; t < 4; t++)
        Wt[(size_t)(n0 + ty + 8 * t) * EE + k0 + tx] = tf32r(tile[tx][ty + 8 * t]);
}

// ---------------------------------------------------------------------------
// tf32 mma.sync GEMM: C[4096,1024] = A[4096,1024] @ Wt[1024(N),1024(K)]^T
// mode 0: dense + bias; mode 1: scatter [B,H,L,D]; mode 2: scatter [B,H,D,S]^T
// ---------------------------------------------------------------------------
#define GA0   0
#define GA1   16384
#define GB0   32768
#define GB1   49152
#define GSMEM (65536 + 1024)

__global__ __launch_bounds__(256)
void gemm_mma_kernel(const float* __restrict__ A, const float* __restrict__ Bt,
                     const float* __restrict__ bias, float* __restrict__ C,
                     int mode, int L)
{
    extern __shared__ char dyn_sm[];
    char* sm = (char*)(((uintptr_t)dyn_sm + 1023) & ~(uintptr_t)1023);
    const uint32_t sb = smem_u32(sm);

    const int tid  = threadIdx.x;
    const int wid  = tid >> 5;
    const int lane = tid & 31;
    const int wm   = wid & 3;
    const int wn   = wid >> 2;
    const int m0 = blockIdx.y * 128;
    const int n0 = blockIdx.x * 128;

    const float* Ap = A  + (size_t)m0 * 1024;
    const float* Bp = Bt + (size_t)n0 * 1024;

    const int lrow  = ((lane >> 3) & 1) * 8 + (lane & 7);
    const int klane = lane >> 4;

    uint32_t aoff[2], asw[2], boff[4], bsw[4];
#pragma unroll
    for (int mt = 0; mt < 2; mt++) {
        int r = wm * 32 + mt * 16 + lrow;
        aoff[mt] = (uint32_t)r * 128;
        asw[mt]  = (uint32_t)(r & 7);
    }
#pragma unroll
    for (int nt = 0; nt < 4; nt++) {
        int r = wn * 64 + nt * 16 + lrow;
        boff[nt] = (uint32_t)r * 128;
        bsw[nt]  = (uint32_t)(r & 7);
    }

    float acc[2][8][4];
#pragma unroll
    for (int mt = 0; mt < 2; mt++)
#pragma unroll
        for (int nt = 0; nt < 8; nt++)
#pragma unroll
            for (int c = 0; c < 4; c++) acc[mt][nt][c] = 0.f;

    auto load_tile = [&](int buf, int kt) {
        const int k0 = kt * 32;
        const uint32_t ao = buf ? GA1 : GA0;
        const uint32_t bo = buf ? GB1 : GB0;
#pragma unroll
        for (int t = 0; t < 4; t++) {
            int idx = tid + t * 256;
            int r = idx >> 3, c4 = idx & 7;
            uint32_t sw = SWZ128((uint32_t)(r * 128 + c4 * 16));
            float4 va = *(const float4*)(Ap + (size_t)r * 1024 + k0 + c4 * 4);
            float4 wa;
            wa.x = tf32r(va.x); wa.y = tf32r(va.y); wa.z = tf32r(va.z); wa.w = tf32r(va.w);
            *(float4*)(sm + ao + sw) = wa;
            *(float4*)(sm + bo + sw) = *(const float4*)(Bp + (size_t)r * 1024 + k0 + c4 * 4);
        }
    };

    auto compute = [&](int buf) {
        const uint32_t ab = sb + (buf ? GA1 : GA0);
        const uint32_t bb = sb + (buf ? GB1 : GB0);
#pragma unroll
        for (int k8 = 0; k8 < 4; k8++) {
            const uint32_t kc = (uint32_t)(k8 * 2 + klane);
            uint32_t af[2][4], bf[4][4];
#pragma unroll
            for (int mt = 0; mt < 2; mt++)
                ldsm4(af[mt], ab + aoff[mt] + ((kc ^ asw[mt]) << 4));
#pragma unroll
            for (int nt = 0; nt < 4; nt++)
                ldsm4(bf[nt], bb + boff[nt] + ((kc ^ bsw[nt]) << 4));
#pragma unroll
            for (int mt = 0; mt < 2; mt++)
#pragma unroll
                for (int n8 = 0; n8 < 8; n8++) {
                    int bt = n8 >> 1, sub = n8 & 1;
                    mma_tf32(acc[mt][n8], af[mt], bf[bt][sub], bf[bt][sub + 2]);
                }
        }
    };

    load_tile(0, 0);
    __syncthreads();

#pragma unroll 1
    for (int kt = 0; kt < 32; kt++) {
        const int p = kt & 1;
        if (kt < 31) load_tile(1 - p, kt + 1);
        compute(p);
        __syncthreads();
    }

    const int rbase = lane >> 2;
    const int cbase = 2 * (lane & 3);
#pragma unroll
    for (int mt = 0; mt < 2; mt++) {
#pragma unroll
        for (int nt = 0; nt < 8; nt++) {
            int n = n0 + wn * 64 + nt * 8 + cbase;
#pragma unroll
            for (int half = 0; half < 2; half++) {
                int m = m0 + wm * 32 + mt * 16 + rbase + half * 8;
                float2 v;
                v.x = acc[mt][nt][half * 2 + 0];
                v.y = acc[mt][nt][half * 2 + 1];
                if (mode == 0) {
                    v.x += bias[n];
                    v.y += bias[n + 1];
                    *(float2*)&C[(size_t)m * 1024 + n] = v;
                } else if (mode == 1) {
                    int b = m / L, l = m % L;
                    size_t o = (((size_t)(b * HH + (n >> 6)) * L + l) * DH) + (n & 63);
                    *(float2*)&C[o] = v;
                } else {
                    // mode 2: Vt[b,h,d,s] = C[m=(b,s)][n=(h,d)]
                    int b = m / L, s = m % L;
                    size_t o = (((size_t)(b * HH + (n >> 6)) * DH) + (n & 63)) * (size_t)L + s;
                    C[o]     = v.x;
                    C[o + L] = v.y;   // d+1 row (n,n+1 never cross a d-64 boundary)
                }
            }
        }
    }
}

// ---------------------------------------------------------------------------
// Tensor-core attention: one block = (b,h) x 32 t-rows, 512 threads (16 warps).
// Phase 1: S = tf32-MMA(Q,K^T) + additive mask -> s_s [32][1036]
// Phase 2: softmax (raw fp32 -> attn_out; tf32-rounded -> s_s)
// Phase 3: O = tf32-MMA(P, V) via V^T tiles, k-split 2 + smem reduction
// ---------------------------------------------------------------------------
#define AT 32
#define SPITCH 1036
#define S_S   0
#define S_Q   33152
#define S_KV  35200
#define S_RED 43392
#define ATTN_FLOATS 45568   // 182272 bytes

__global__ __launch_bounds__(512)
void attn_kernel(const float* __restrict__ Q, const float* __restrict__ K,
                 const float* __restrict__ Vt,
                 const float* __restrict__ tpad, const float* __restrict__ spad,
                 const float* __restrict__ amask, const int* __restrict__ causal_p,
                 float* __restrict__ attn_out, float* __restrict__ P)
{
    extern __shared__ float smf[];
    float* s_s   = smf + S_S;
    float* s_red = smf + S_RED;
    const uint32_t ss_b  = smem_u32(smf + S_S);
    const uint32_t sq_b  = smem_u32(smf + S_Q);
    const uint32_t skv_b = smem_u32(smf + S_KV);

    const int tid = threadIdx.x;
    const int bh  = blockIdx.y;
    const int b   = bh >> 4;
    const int h   = bh & 15;
    const int t0  = blockIdx.x * AT;
    const bool causal = (causal_p[0] != 0);

    const size_t qbase  = ((size_t)bh * TT + t0) * DH;
    const size_t kbase  = (size_t)bh * SS * DH;
    const size_t vtbase = (size_t)bh * DH * SS;

    const int lane  = tid & 31;
    const int wid   = tid >> 5;
    const int lrow  = ((lane >> 3) & 1) * 8 + (lane & 7);
    const int klane = lane >> 4;
    const int rbase = lane >> 2;
    const int cbase = 2 * (lane & 3);

    // ---- load Q tile 32x64 (scaled, tf32), swizzled rows of 256B ----
    {
        int r = tid >> 4, c = tid & 15;   // 512 float4 chunks exactly
        float4 v = *(const float4*)&Q[qbase + (size_t)r * DH + c * 4];
        float4 w;
        w.x = tf32r(v.x * 0.125f); w.y = tf32r(v.y * 0.125f);
        w.z = tf32r(v.z * 0.125f); w.w = tf32r(v.w * 0.125f);
        *(float4*)((char*)smf + S_Q * 4 + r * 256 + ((c ^ (r & 7)) << 4)) = w;
    }
    __syncthreads();

    // ---- phase 1: warp = (wm2, wn8); preload Q fragments ----
    const int wm2 = wid & 1;
    const int wn8 = wid >> 1;
    const int arow = wm2 * 16 + lrow;
    uint32_t qf[8][4];
#pragma unroll
    for (int k8 = 0; k8 < 8; k8++) {
        uint32_t kc = (uint32_t)(k8 * 2 + klane);
        ldsm4(qf[k8], sq_b + arow * 256 + ((kc ^ (uint32_t)(arow & 7)) << 4));
    }

    const int brow = wn8 * 16 + lrow;
#pragma unroll 1
    for (int c0 = 0; c0 < SS; c0 += 128) {
        __syncthreads();
        // load K tile 128x64, tf32, swizzled
#pragma unroll
        for (int t = 0; t < 4; t++) {
            int idx = tid + t * 512;
            int r = idx >> 4, c = idx & 15;
            float4 v = *(const float4*)&K[kbase + (size_t)(c0 + r) * DH + c * 4];
            float4 w;
            w.x = tf32r(v.x); w.y = tf32r(v.y); w.z = tf32r(v.z); w.w = tf32r(v.w);
            *(float4*)((char*)smf + S_KV * 4 + r * 256 + ((c ^ (r & 7)) << 4)) = w;
        }
        __syncthreads();

        float acc[2][4];
#pragma unroll
        for (int n8 = 0; n8 < 2; n8++)
#pragma unroll
            for (int c = 0; c < 4; c++) acc[n8][c] = 0.f;

#pragma unroll
        for (int k8 = 0; k8 < 8; k8++) {
            uint32_t kc = (uint32_t)(k8 * 2 + klane);
            uint32_t bf[4];
            ldsm4(bf, skv_b + brow * 256 + ((kc ^ (uint32_t)(brow & 7)) << 4));
            mma_tf32(acc[0], qf[k8], bf[0], bf[2]);
            mma_tf32(acc[1], qf[k8], bf[1], bf[3]);
        }

        // scores + additive mask -> s_s
#pragma unroll
        for (int n8 = 0; n8 < 2; n8++) {
            int sc = c0 + wn8 * 16 + n8 * 8 + cbase;
            float sp0 = spad[b * SS + sc];
            float sp1 = spad[b * SS + sc + 1];
#pragma unroll
            for (int half = 0; half < 2; half++) {
                int tr = wm2 * 16 + rbase + half * 8;
                int t = t0 + tr;
                float2 am = *(const float2*)&amask[((size_t)b * TT + t) * SS + sc];
                float tm = tpad[b * TT + t];
                float m0 = tm * sp0 * am.x;
                float m1 = tm * sp1 * am.y;
                if (causal) {
                    if (sc > t)     m0 = 0.f;
                    if (sc + 1 > t) m1 = 0.f;
                }
                s_s[tr * SPITCH + sc]     = acc[n8][half * 2 + 0] + m0;
                s_s[tr * SPITCH + sc + 1] = acc[n8][half * 2 + 1] + m1;
            }
        }
    }
    __syncthreads();

    // ---- phase 2: softmax, 16 lanes per row ----
    {
        const int r   = tid >> 4;
        const int l16 = tid & 15;
        float* row = s_s + r * SPITCH;

        float mx = -1e30f;
        for (int c = l16; c < SS; c += 16) mx = fmaxf(mx, row[c]);
#pragma unroll
        for (int o = 8; o > 0; o >>= 1) mx = fmaxf(mx, __shfl_xor_sync(0xffffffffu, mx, o, 16));

        float sum = 0.f;
        for (int c = l16; c < SS; c += 16) {
            float e = __expf(row[c] - mx);
            row[c] = e;
            sum += e;
        }
#pragma unroll
        for (int o = 8; o > 0; o >>= 1) sum += __shfl_xor_sync(0xffffffffu, sum, o, 16);

        float inv = 1.f / sum;
        size_t abase = ((size_t)bh * TT + (t0 + r)) * SS;
        for (int c = l16; c < SS; c += 16) {
            float p = row[c] * inv;
            if (attn_out) attn_out[abase + c] = p;   // full precision out
            row[c] = tf32r(p);                        // tf32 for PV MMA
        }
    }
    __syncthreads();

    // ---- phase 3: O = P @ V, warp = (kh, wm2b, wn4), k-split 2 ----
    const int kh   = wid >> 3;
    const int wm2b = (wid >> 2) & 1;
    const int wn4  = wid & 3;
    const int arow3 = wm2b * 16 + lrow;
    const int brow3 = wn4 * 16 + lrow;

    float oacc[2][4];
#pragma unroll
    for (int n8 = 0; n8 < 2; n8++)
#pragma unroll
        for (int c = 0; c < 4; c++) oacc[n8][c] = 0.f;

#pragma unroll 1
    for (int c0 = 0; c0 < SS; c0 += 128) {
        __syncthreads();
        // load V^T tile 64 x 128 (tf32), swizzled rows of 512B
#pragma unroll
        for (int t = 0; t < 4; t++) {
            int idx = tid + t * 512;
            int d = idx >> 5, c = idx & 31;
            float4 v = *(const float4*)&Vt[vtbase + (size_t)d * SS + c0 + c * 4];
            float4 w;
            w.x = tf32r(v.x); w.y = tf32r(v.y); w.z = tf32r(v.z); w.w = tf32r(v.w);
            *(float4*)((char*)smf + S_KV * 4 + d * 512 + ((c ^ (d & 7)) << 4)) = w;
        }
        __syncthreads();

#pragma unroll
        for (int k8 = 0; k8 < 8; k8++) {
            uint32_t kcA = (uint32_t)((c0 >> 2) + kh * 16 + k8 * 2 + klane);
            uint32_t af[4];
            ldsm4(af, ss_b + arow3 * (SPITCH * 4) + kcA * 16);
            uint32_t kcB = (uint32_t)(kh * 16 + k8 * 2 + klane);
            uint32_t bf[4];
            ldsm4(bf, skv_b + brow3 * 512 + ((kcB ^ (uint32_t)(brow3 & 7)) << 4));
            mma_tf32(oacc[0], af, bf[0], bf[2]);
            mma_tf32(oacc[1], af, bf[1], bf[3]);
        }
    }

    // k-split reduction via s_red (pitch 68), then write P
    if (kh == 0) {
#pragma unroll
        for (int n8 = 0; n8 < 2; n8++)
#pragma unroll
            for (int half = 0; half < 2; half++) {
                int rr = wm2b * 16 + rbase + half * 8;
                int cc = wn4 * 16 + n8 * 8 + cbase;
                s_red[rr * 68 + cc]     = oacc[n8][half * 2 + 0];
                s_red[rr * 68 + cc + 1] = oacc[n8][half * 2 + 1];
            }
    }
    __syncthreads();
    if (kh == 1) {
#pragma unroll
        for (int n8 = 0; n8 < 2; n8++)
#pragma unroll
            for (int half = 0; half < 2; half++) {
                int rr = wm2b * 16 + rbase + half * 8;
                int cc = wn4 * 16 + n8 * 8 + cbase;
                float2 v;
                v.x = oacc[n8][half * 2 + 0] + s_red[rr * 68 + cc];
                v.y = oacc[n8][half * 2 + 1] + s_red[rr * 68 + cc + 1];
                int t = t0 + rr;
                *(float2*)&P[((size_t)t * BX + b) * EE + h * DH + cc] = v;
            }
    }
}

// ---------------------------------------------------------------------------
// Launch
// ---------------------------------------------------------------------------
extern "C" void kernel_launch(void* const* d_in, const int* in_sizes, int n_in,
                              void* d_out, int out_size)
{
    const float* src   = (const float*)d_in[0];
    const float* tgt   = (const float*)d_in[1];
    const float* spad  = (const float*)d_in[2];
    const float* tpad  = (const float*)d_in[3];
    const float* amask = (const float*)d_in[4];
    const int*   caus  = (const int*)  d_in[5];
    const float* Wq    = (const float*)d_in[6];
    const float* Wk    = (const float*)d_in[7];
    const float* Wv    = (const float*)d_in[8];
    const float* Wo    = (const float*)d_in[9];
    const float* bo    = (const float*)d_in[10];

    const size_t OUT_N  = (size_t)TT * BX * EE;
    const size_t ATTN_N = (size_t)BX * HH * TT * SS;

    float* out_p  = nullptr;
    float* attn_p = nullptr;
    if ((size_t)out_size == OUT_N + ATTN_N) {
        out_p  = (float*)d_out;
        attn_p = (float*)d_out + OUT_N;
    } else if ((size_t)out_size == ATTN_N) {
        attn_p = (float*)d_out;
    } else {
        out_p  = (float*)d_out;
    }

    float *Qp, *Kp, *Vtp, *Pp, *Wtp;
    cudaGetSymbolAddress((void**)&Qp, g_Q);
    cudaGetSymbolAddress((void**)&Kp, g_K);
    cudaGetSymbolAddress((void**)&Vtp, g_Vt);
    cudaGetSymbolAddress((void**)&Pp, g_P);
    cudaGetSymbolAddress((void**)&Wtp, g_Wt);

    const int ATTN_SMEM = ATTN_FLOATS * (int)sizeof(float);
    cudaFuncSetAttribute(attn_kernel, cudaFuncAttributeMaxDynamicSharedMemorySize, ATTN_SMEM);
    cudaFuncSetAttribute(gemm_mma_kernel, cudaFuncAttributeMaxDynamicSharedMemorySize, GSMEM);

    dim3 tgrid(32, 32), tblk(256);
    transpose_tf32_kernel<<<tgrid, tblk>>>(Wq, Wtp + 0 * (size_t)EE * EE);
    transpose_tf32_kernel<<<tgrid, tblk>>>(Wk, Wtp + 1 * (size_t)EE * EE);
    transpose_tf32_kernel<<<tgrid, tblk>>>(Wv, Wtp + 2 * (size_t)EE * EE);
    transpose_tf32_kernel<<<tgrid, tblk>>>(Wo, Wtp + 3 * (size_t)EE * EE);

    dim3 ggrid(8, 32), gblk(256);
    gemm_mma_kernel<<<ggrid, gblk, GSMEM>>>(tgt, Wtp + 0 * (size_t)EE * EE, nullptr, Qp, 1, TT);
    gemm_mma_kernel<<<ggrid, gblk, GSMEM>>>(src, Wtp + 1 * (size_t)EE * EE, nullptr, Kp, 1, SS);
    gemm_mma_kernel<<<ggrid, gblk, GSMEM>>>(src, Wtp + 2 * (size_t)EE * EE, nullptr, Vtp, 2, SS);

    dim3 agrid(TT / AT, BX * HH);
    attn_kernel<<<agrid, dim3(512), ATTN_SMEM>>>(Qp, Kp, Vtp, tpad, spad, amask,
                                                 caus, attn_p, Pp);

    if (out_p) {
        gemm_mma_kernel<<<ggrid, gblk, GSMEM>>>(Pp, Wtp + 3 * (size_t)EE * EE, bo, out_p, 0, TT);
    }
}

// round 5
// speedup vs baseline: 3.4285x; 1.2372x over previous
#include <cuda_runtime.h>
#include <cuda_bf16.h>
#include <math.h>
#include <cstdint>

// Problem constants
#define BX   4
#define TT   1024
#define SS   1024
#define EE   1024
#define HH   16
#define DH   64

// Scratch (device globals; no allocation allowed)
__device__ float g_Q[BX * HH * TT * DH];   // [B,H,T,D]  tf32, pre-scaled by 1/8
__device__ float g_K[BX * HH * SS * DH];   // [B,H,S,D]  tf32
__device__ float g_Vt[BX * HH * DH * SS];  // [B,H,D,S]  tf32
__device__ float g_P[TT * BX * EE];        // [T,B,E]    tf32
__device__ float g_Wt[4 * EE * EE];        // W^T [N,K]  tf32
__device__ float g_Ar[BX * TT * EE];       // tgt tf32-rounded
__device__ float g_Br[BX * SS * EE];       // src tf32-rounded

// ---------------------------------------------------------------------------
// Helpers
// ---------------------------------------------------------------------------
__device__ __forceinline__ uint32_t smem_u32(const void* p) {
    uint32_t a;
    asm("{ .reg .u64 t; cvta.to.shared.u64 t, %1; cvt.u32.u64 %0, t; }" : "=r"(a) : "l"(p));
    return a;
}
__device__ __forceinline__ float tf32r(float x) {
    uint32_t u;
    asm("cvt.rna.tf32.f32 %0, %1;" : "=r"(u) : "f"(x));
    return __uint_as_float(u);
}
#define SWZ128(off) ((off) ^ (((off) >> 3) & 0x70))

__device__ __forceinline__ void cp16(uint32_t dst, const void* src) {
    asm volatile("cp.async.cg.shared.global [%0], [%1], 16;" :: "r"(dst), "l"(src));
}
#define CP_COMMIT() asm volatile("cp.async.commit_group;" ::: "memory")
#define CP_WAIT1()  asm volatile("cp.async.wait_group 1;" ::: "memory")

__device__ __forceinline__ void ldsm4(uint32_t* r, uint32_t addr) {
    asm volatile("ldmatrix.sync.aligned.m8n8.x4.shared.b16 {%0,%1,%2,%3}, [%4];"
                 : "=r"(r[0]), "=r"(r[1]), "=r"(r[2]), "=r"(r[3]) : "r"(addr));
}
__device__ __forceinline__ void mma_tf32(float* d, const uint32_t* a, uint32_t b0, uint32_t b1) {
    asm volatile("mma.sync.aligned.m16n8k8.row.col.f32.tf32.tf32.f32 "
                 "{%0,%1,%2,%3}, {%4,%5,%6,%7}, {%8,%9}, {%0,%1,%2,%3};"
                 : "+f"(d[0]), "+f"(d[1]), "+f"(d[2]), "+f"(d[3])
                 : "r"(a[0]), "r"(a[1]), "r"(a[2]), "r"(a[3]), "r"(b0), "r"(b1));
}

// ---------------------------------------------------------------------------
// Elementwise tf32 rounding copies (z selects tensor)
// ---------------------------------------------------------------------------
__global__ __launch_bounds__(256)
void round_tf32_kernel(const float* __restrict__ a, const float* __restrict__ b,
                       float* __restrict__ oa, float* __restrict__ ob)
{
    const float* src = blockIdx.z ? b : a;
    float* dst = blockIdx.z ? ob : oa;
    const int n4 = (BX * TT * EE) / 4;
    for (int i = blockIdx.x * 256 + threadIdx.x; i < n4; i += gridDim.x * 256) {
        float4 v = ((const float4*)src)[i];
        v.x = tf32r(v.x); v.y = tf32r(v.y); v.z = tf32r(v.z); v.w = tf32r(v.w);
        ((float4*)dst)[i] = v;
    }
}

// ---------------------------------------------------------------------------
// Weight transpose + tf32 round, 4 weights in one launch (z selects)
// ---------------------------------------------------------------------------
__global__ __launch_bounds__(256)
void transpose_tf32_kernel(const float* __restrict__ W0, const float* __restrict__ W1,
                           const float* __restrict__ W2, const float* __restrict__ W3,
                           float* __restrict__ WtBase)
{
    __shared__ float tile[32][33];
    const int z = blockIdx.z;
    const float* W = (z == 0) ? W0 : (z == 1) ? W1 : (z == 2) ? W2 : W3;
    float* Wt = WtBase + (size_t)z * EE * EE;
    const int k0 = blockIdx.y * 32, n0 = blockIdx.x * 32;
    const int tx = threadIdx.x & 31, ty = threadIdx.x >> 5;
#pragma unroll
    for (int t = 0; t < 4; t++)
        tile[ty + 8 * t][tx] = W[(size_t)(k0 + ty + 8 * t) * EE + n0 + tx];
    __syncthreads();
#pragma unroll
    for (int t = 0; t < 4; t++)
        Wt[(size_t)(n0 + ty + 8 * t) * EE + k0 + tx] = tf32r(tile[tx][ty + 8 * t]);
}

// ---------------------------------------------------------------------------
// tf32 mma.sync GEMM body: C[4096,1024] = A[4096,1024] @ Wt[1024,1024]^T
// 3-stage cp.async pipeline, 128x128 block, 8 warps.
// mode 0: dense + bias (fp32); mode 1: scatter [B,H,L,D] tf32r(v*scale);
// mode 2: scatter [B,H,D,S]^T tf32r(v)
// ---------------------------------------------------------------------------
#define GSMEM (3 * 32768 + 1024)

__device__ __forceinline__ void gemm_body(
    const float* __restrict__ A, const float* __restrict__ Bt,
    const float* __restrict__ bias, float* __restrict__ C,
    int mode, float scale, int L)
{
    extern __shared__ char dyn_sm[];
    char* sm = (char*)(((uintptr_t)dyn_sm + 1023) & ~(uintptr_t)1023);
    const uint32_t sb = smem_u32(sm);

    const int tid  = threadIdx.x;
    const int wid  = tid >> 5;
    const int lane = tid & 31;
    const int wm   = wid & 3;
    const int wn   = wid >> 2;
    const int m0 = blockIdx.y * 128;
    const int n0 = blockIdx.x * 128;

    const float* Ap = A  + (size_t)m0 * 1024;
    const float* Bp = Bt + (size_t)n0 * 1024;

    const int lrow  = ((lane >> 3) & 1) * 8 + (lane & 7);
    const int klane = lane >> 4;

    uint32_t aoff[2], asw[2], boff[4], bsw[4];
#pragma unroll
    for (int mt = 0; mt < 2; mt++) {
        int r = wm * 32 + mt * 16 + lrow;
        aoff[mt] = (uint32_t)r * 128;
        asw[mt]  = (uint32_t)(r & 7);
    }
#pragma unroll
    for (int nt = 0; nt < 4; nt++) {
        int r = wn * 64 + nt * 16 + lrow;
        boff[nt] = (uint32_t)r * 128;
        bsw[nt]  = (uint32_t)(r & 7);
    }

    float acc[2][8][4];
#pragma unroll
    for (int mt = 0; mt < 2; mt++)
#pragma unroll
        for (int nt = 0; nt < 8; nt++)
#pragma unroll
            for (int c = 0; c < 4; c++) acc[mt][nt][c] = 0.f;

    auto prefetch = [&](int st, int kt) {
        const int k0 = kt * 32;
        const uint32_t ao = sb + st * 32768;
        const uint32_t bo = ao + 16384;
#pragma unroll
        for (int t = 0; t < 4; t++) {
            int idx = tid + t * 256;
            int r = idx >> 3, c4 = idx & 7;
            uint32_t sw = SWZ128((uint32_t)(r * 128 + c4 * 16));
            cp16(ao + sw, Ap + (size_t)r * 1024 + k0 + c4 * 4);
            cp16(bo + sw, Bp + (size_t)r * 1024 + k0 + c4 * 4);
        }
    };

    prefetch(0, 0); CP_COMMIT();
    prefetch(1, 1); CP_COMMIT();

#pragma unroll 1
    for (int kt = 0; kt < 32; kt++) {
        CP_WAIT1();
        __syncthreads();
        if (kt + 2 < 32) prefetch((kt + 2) % 3, kt + 2);
        CP_COMMIT();

        const uint32_t ab = sb + (kt % 3) * 32768;
        const uint32_t bb = ab + 16384;
#pragma unroll
        for (int k8 = 0; k8 < 4; k8++) {
            const uint32_t kc = (uint32_t)(k8 * 2 + klane);
            uint32_t af[2][4], bf[4][4];
#pragma unroll
            for (int mt = 0; mt < 2; mt++)
                ldsm4(af[mt], ab + aoff[mt] + ((kc ^ asw[mt]) << 4));
#pragma unroll
            for (int nt = 0; nt < 4; nt++)
                ldsm4(bf[nt], bb + boff[nt] + ((kc ^ bsw[nt]) << 4));
#pragma unroll
            for (int mt = 0; mt < 2; mt++)
#pragma unroll
                for (int n8 = 0; n8 < 8; n8++) {
                    int bt = n8 >> 1, sub = n8 & 1;
                    mma_tf32(acc[mt][n8], af[mt], bf[bt][sub], bf[bt][sub + 2]);
                }
        }
    }

    const int rbase = lane >> 2;
    const int cbase = 2 * (lane & 3);
#pragma unroll
    for (int mt = 0; mt < 2; mt++) {
#pragma unroll
        for (int nt = 0; nt < 8; nt++) {
            int n = n0 + wn * 64 + nt * 8 + cbase;
#pragma unroll
            for (int half = 0; half < 2; half++) {
                int m = m0 + wm * 32 + mt * 16 + rbase + half * 8;
                float2 v;
                v.x = acc[mt][nt][half * 2 + 0];
                v.y = acc[mt][nt][half * 2 + 1];
                if (mode == 0) {
                    v.x += bias[n];
                    v.y += bias[n + 1];
                    *(float2*)&C[(size_t)m * 1024 + n] = v;
                } else if (mode == 1) {
                    int b = m / L, l = m % L;
                    size_t o = (((size_t)(b * HH + (n >> 6)) * L + l) * DH) + (n & 63);
                    v.x = tf32r(v.x * scale);
                    v.y = tf32r(v.y * scale);
                    *(float2*)&C[o] = v;
                } else {
                    int b = m / L, s = m % L;
                    size_t o = (((size_t)(b * HH + (n >> 6)) * DH) + (n & 63)) * (size_t)L + s;
                    C[o]     = tf32r(v.x);
                    C[o + L] = tf32r(v.y);
                }
            }
        }
    }
}

// Merged QKV: z=0 Q (scale 1/8), z=1 K, z=2 V^T
__global__ __launch_bounds__(256)
void gemm_qkv_kernel(const float* __restrict__ Atgt, const float* __restrict__ Asrc,
                     const float* __restrict__ Wt,
                     float* __restrict__ Cq, float* __restrict__ Ck, float* __restrict__ Cvt)
{
    const int z = blockIdx.z;
    const float* A = (z == 0) ? Atgt : Asrc;
    const float* W = Wt + (size_t)z * EE * EE;
    float* C = (z == 0) ? Cq : (z == 1) ? Ck : Cvt;
    gemm_body(A, W, nullptr, C, (z == 2) ? 2 : 1, (z == 0) ? 0.125f : 1.0f, (z == 0) ? TT : SS);
}

__global__ __launch_bounds__(256)
void gemm_out_kernel(const float* __restrict__ A, const float* __restrict__ Wt,
                     const float* __restrict__ bias, float* __restrict__ C)
{
    gemm_body(A, Wt, bias, C, 0, 1.0f, TT);
}

// ---------------------------------------------------------------------------
// Tensor-core attention, cp.async pipelined. One block = (b,h) x 32 t-rows,
// 512 threads (16 warps). Inputs Q/K/Vt already tf32 (Q pre-scaled 1/8).
// ---------------------------------------------------------------------------
#define AT 32
#define SPITCH 1036
#define S_S   0
#define S_Q   33152
#define S_RED 35200
#define S_X   37376
#define X_K    S_X                 // 8192 floats (32KB) phase-1 K tile
#define X_M0  (S_X + 8192)         // 4224 floats mask buf 0 (pitch 132)
#define X_M1  (S_X + 8192 + 4224)  // 4224 floats mask buf 1
#define ATTN_FLOATS (S_X + 16640)  // 54016 floats = 216064 B

__global__ __launch_bounds__(512)
void attn_kernel(const float* __restrict__ Q, const float* __restrict__ K,
                 const float* __restrict__ Vt,
                 const float* __restrict__ tpad, const float* __restrict__ spad,
                 const float* __restrict__ amask, const int* __restrict__ causal_p,
                 float* __restrict__ attn_out, float* __restrict__ P)
{
    extern __shared__ float smf[];
    float* s_s   = smf + S_S;
    float* s_red = smf + S_RED;
    const uint32_t ss_b = smem_u32(smf + S_S);
    const uint32_t sq_b = smem_u32(smf + S_Q);
    const uint32_t sx_b = smem_u32(smf + S_X);
    const uint32_t m0_b = smem_u32(smf + X_M0);
    const uint32_t m1_b = smem_u32(smf + X_M1);

    const int tid = threadIdx.x;
    const int bh  = blockIdx.y;
    const int b   = bh >> 4;
    const int h   = bh & 15;
    const int t0  = blockIdx.x * AT;
    const bool causal = (causal_p[0] != 0);

    const size_t qbase  = ((size_t)bh * TT + t0) * DH;
    const size_t kbase  = (size_t)bh * SS * DH;
    const size_t vtbase = (size_t)bh * DH * SS;

    const int lane  = tid & 31;
    const int wid   = tid >> 5;
    const int lrow  = ((lane >> 3) & 1) * 8 + (lane & 7);
    const int klane = lane >> 4;
    const int rbase = lane >> 2;
    const int cbase = 2 * (lane & 3);

    auto prefetch_mask = [&](int c0, uint32_t mb) {
#pragma unroll
        for (int t = 0; t < 2; t++) {
            int idx = tid + t * 512;
            int r = idx >> 5, c16 = idx & 31;
            cp16(mb + r * 528 + c16 * 16,
                 amask + ((size_t)b * TT + t0 + r) * SS + c0 + c16 * 4);
        }
    };
    auto prefetch_k = [&](int c0) {
#pragma unroll
        for (int t = 0; t < 4; t++) {
            int idx = tid + t * 512;
            int r = idx >> 4, c = idx & 15;
            cp16(sx_b + r * 256 + ((c ^ (r & 7)) << 4),
                 K + kbase + (size_t)(c0 + r) * DH + c * 4);
        }
    };

    // prologue: Q tile + mask(0)
    {
        int r = tid >> 4, c = tid & 15;
        cp16(sq_b + r * 256 + ((c ^ (r & 7)) << 4), Q + qbase + (size_t)r * DH + c * 4);
    }
    CP_COMMIT();
    prefetch_mask(0, m0_b);
    CP_COMMIT();
    CP_WAIT1();         // Q ready (mask0 may be pending)
    __syncthreads();

    // phase-1 warp layout: (wm2, wn8); preload Q fragments
    const int wm2 = wid & 1;
    const int wn8 = wid >> 1;
    const int arow = wm2 * 16 + lrow;
    uint32_t qf[8][4];
#pragma unroll
    for (int k8 = 0; k8 < 8; k8++) {
        uint32_t kc = (uint32_t)(k8 * 2 + klane);
        ldsm4(qf[k8], sq_b + arow * 256 + ((kc ^ (uint32_t)(arow & 7)) << 4));
    }
    const int brow = wn8 * 16 + lrow;

    // ---------------- Phase 1: scores ----------------
#pragma unroll 1
    for (int it = 0; it < 8; it++) {
        const int c0 = it * 128;
        prefetch_k(c0);
        CP_COMMIT();
        if (it < 7) prefetch_mask(c0 + 128, ((it + 1) & 1) ? m1_b : m0_b);
        CP_COMMIT();
        CP_WAIT1();        // K(it) + mask(it) done; mask(it+1) may be pending
        __syncthreads();

        float acc[2][4];
#pragma unroll
        for (int n8 = 0; n8 < 2; n8++)
#pragma unroll
            for (int c = 0; c < 4; c++) acc[n8][c] = 0.f;

#pragma unroll
        for (int k8 = 0; k8 < 8; k8++) {
            uint32_t kc = (uint32_t)(k8 * 2 + klane);
            uint32_t bf[4];
            ldsm4(bf, sx_b + brow * 256 + ((kc ^ (uint32_t)(brow & 7)) << 4));
            mma_tf32(acc[0], qf[k8], bf[0], bf[2]);
            mma_tf32(acc[1], qf[k8], bf[1], bf[3]);
        }

        const float* s_m = smf + ((it & 1) ? X_M1 : X_M0);
#pragma unroll
        for (int n8 = 0; n8 < 2; n8++) {
            int scl = wn8 * 16 + n8 * 8 + cbase;
            int sc = c0 + scl;
            float sp0 = spad[b * SS + sc];
            float sp1 = spad[b * SS + sc + 1];
#pragma unroll
            for (int half = 0; half < 2; half++) {
                int tr = wm2 * 16 + rbase + half * 8;
                int t = t0 + tr;
                float2 am = *(const float2*)&s_m[tr * 132 + scl];
                float tm = tpad[b * TT + t];
                float m0 = tm * sp0 * am.x;
                float m1 = tm * sp1 * am.y;
                if (causal) {
                    if (sc > t)     m0 = 0.f;
                    if (sc + 1 > t) m1 = 0.f;
                }
                s_s[tr * SPITCH + sc]     = acc[n8][half * 2 + 0] + m0;
                s_s[tr * SPITCH + sc + 1] = acc[n8][half * 2 + 1] + m1;
            }
        }
        __syncthreads();
    }

    // ---------------- Phase 2: softmax (16 lanes / row, float4) ----------------
    {
        const int r   = tid >> 4;
        const int l16 = tid & 15;
        float* row = s_s + r * SPITCH;

        float mx = -1e30f;
#pragma unroll
        for (int i = 0; i < 16; i++) {
            float4 v = *(float4*)&row[l16 * 4 + i * 64];
            mx = fmaxf(mx, fmaxf(fmaxf(v.x, v.y), fmaxf(v.z, v.w)));
        }
#pragma unroll
        for (int o = 8; o > 0; o >>= 1) mx = fmaxf(mx, __shfl_xor_sync(0xffffffffu, mx, o, 16));

        float sum = 0.f;
#pragma unroll
        for (int i = 0; i < 16; i++) {
            float4 v = *(float4*)&row[l16 * 4 + i * 64];
            v.x = __expf(v.x - mx); v.y = __expf(v.y - mx);
            v.z = __expf(v.z - mx); v.w = __expf(v.w - mx);
            *(float4*)&row[l16 * 4 + i * 64] = v;
            sum += v.x + v.y + v.z + v.w;
        }
#pragma unroll
        for (int o = 8; o > 0; o >>= 1) sum += __shfl_xor_sync(0xffffffffu, sum, o, 16);

        float inv = 1.f / sum;
        size_t abase = ((size_t)bh * TT + (t0 + r)) * SS;
#pragma unroll
        for (int i = 0; i < 16; i++) {
            float4 v = *(float4*)&row[l16 * 4 + i * 64];
            v.x *= inv; v.y *= inv; v.z *= inv; v.w *= inv;
            if (attn_out) *(float4*)&attn_out[abase + l16 * 4 + i * 64] = v;
            v.x = tf32r(v.x); v.y = tf32r(v.y); v.z = tf32r(v.z); v.w = tf32r(v.w);
            *(float4*)&row[l16 * 4 + i * 64] = v;
        }
    }
    __syncthreads();

    // ---------------- Phase 3: O = P @ V (V^T tiles 64x64, 3-stage) ----------------
    const int kh   = wid >> 3;
    const int wm2b = (wid >> 2) & 1;
    const int wn4  = wid & 3;
    const int arow3 = wm2b * 16 + lrow;
    const int brow3 = wn4 * 16 + lrow;

    auto prefetch_v = [&](int it, int st) {
        const int c0 = it * 64;
        const uint32_t vb = sx_b + st * 16384;
#pragma unroll
        for (int t = 0; t < 2; t++) {
            int idx = tid + t * 512;
            int d = idx >> 4, c = idx & 15;
            cp16(vb + d * 256 + ((c ^ (d & 7)) << 4),
                 Vt + vtbase + (size_t)d * SS + c0 + c * 4);
        }
    };

    float oacc[2][4];
#pragma unroll
    for (int n8 = 0; n8 < 2; n8++)
#pragma unroll
        for (int c = 0; c < 4; c++) oacc[n8][c] = 0.f;

    prefetch_v(0, 0); CP_COMMIT();
    prefetch_v(1, 1); CP_COMMIT();

#pragma unroll 1
    for (int it = 0; it < 16; it++) {
        CP_WAIT1();
        __syncthreads();
        if (it + 2 < 16) prefetch_v(it + 2, (it + 2) % 3);
        CP_COMMIT();

        const int c0 = it * 64;
        const uint32_t vb = sx_b + (it % 3) * 16384;
#pragma unroll
        for (int k8 = 0; k8 < 4; k8++) {
            uint32_t kcA = (uint32_t)((c0 >> 2) + kh * 8 + k8 * 2 + klane);
            uint32_t af[4];
            ldsm4(af, ss_b + arow3 * (SPITCH * 4) + kcA * 16);
            uint32_t kcB = (uint32_t)(kh * 8 + k8 * 2 + klane);
            uint32_t bf[4];
            ldsm4(bf, vb + brow3 * 256 + ((kcB ^ (uint32_t)(brow3 & 7)) << 4));
            mma_tf32(oacc[0], af, bf[0], bf[2]);
            mma_tf32(oacc[1], af, bf[1], bf[3]);
        }
    }

    // k-split reduction via s_red (pitch 68), store P tf32-rounded
    if (kh == 0) {
#pragma unroll
        for (int n8 = 0; n8 < 2; n8++)
#pragma unroll
            for (int half = 0; half < 2; half++) {
                int rr = wm2b * 16 + rbase + half * 8;
                int cc = wn4 * 16 + n8 * 8 + cbase;
                s_red[rr * 68 + cc]     = oacc[n8][half * 2 + 0];
                s_red[rr * 68 + cc + 1] = oacc[n8][half * 2 + 1];
            }
    }
    __syncthreads();
    if (kh == 1) {
#pragma unroll
        for (int n8 = 0; n8 < 2; n8++)
#pragma unroll
            for (int half = 0; half < 2; half++) {
                int rr = wm2b * 16 + rbase + half * 8;
                int cc = wn4 * 16 + n8 * 8 + cbase;
                float2 v;
                v.x = tf32r(oacc[n8][half * 2 + 0] + s_red[rr * 68 + cc]);
                v.y = tf32r(oacc[n8][half * 2 + 1] + s_red[rr * 68 + cc + 1]);
                int t = t0 + rr;
                *(float2*)&P[((size_t)t * BX + b) * EE + h * DH + cc] = v;
            }
    }
}

// ---------------------------------------------------------------------------
// Launch
// ---------------------------------------------------------------------------
extern "C" void kernel_launch(void* const* d_in, const int* in_sizes, int n_in,
                              void* d_out, int out_size)
{
    const float* src   = (const float*)d_in[0];
    const float* tgt   = (const float*)d_in[1];
    const float* spad  = (const float*)d_in[2];
    const float* tpad  = (const float*)d_in[3];
    const float* amask = (const float*)d_in[4];
    const int*   caus  = (const int*)  d_in[5];
    const float* Wq    = (const float*)d_in[6];
    const float* Wk    = (const float*)d_in[7];
    const float* Wv    = (const float*)d_in[8];
    const float* Wo    = (const float*)d_in[9];
    const float* bo    = (const float*)d_in[10];

    const size_t OUT_N  = (size_t)TT * BX * EE;
    const size_t ATTN_N = (size_t)BX * HH * TT * SS;

    float* out_p  = nullptr;
    float* attn_p = nullptr;
    if ((size_t)out_size == OUT_N + ATTN_N) {
        out_p  = (float*)d_out;
        attn_p = (float*)d_out + OUT_N;
    } else if ((size_t)out_size == ATTN_N) {
        attn_p = (float*)d_out;
    } else {
        out_p  = (float*)d_out;
    }

    float *Qp, *Kp, *Vtp, *Pp, *Wtp, *Arp, *Brp;
    cudaGetSymbolAddress((void**)&Qp, g_Q);
    cudaGetSymbolAddress((void**)&Kp, g_K);
    cudaGetSymbolAddress((void**)&Vtp, g_Vt);
    cudaGetSymbolAddress((void**)&Pp, g_P);
    cudaGetSymbolAddress((void**)&Wtp, g_Wt);
    cudaGetSymbolAddress((void**)&Arp, g_Ar);
    cudaGetSymbolAddress((void**)&Brp, g_Br);

    const int ATTN_SMEM = ATTN_FLOATS * (int)sizeof(float);
    cudaFuncSetAttribute(attn_kernel, cudaFuncAttributeMaxDynamicSharedMemorySize, ATTN_SMEM);
    cudaFuncSetAttribute(gemm_qkv_kernel, cudaFuncAttributeMaxDynamicSharedMemorySize, GSMEM);
    cudaFuncSetAttribute(gemm_out_kernel, cudaFuncAttributeMaxDynamicSharedMemorySize, GSMEM);

    // pre-round inputs + transpose weights
    round_tf32_kernel<<<dim3(512, 1, 2), 256>>>(tgt, src, Arp, Brp);
    transpose_tf32_kernel<<<dim3(32, 32, 4), 256>>>(Wq, Wk, Wv, Wo, Wtp);

    // merged QKV projections
    gemm_qkv_kernel<<<dim3(8, 32, 3), 256, GSMEM>>>(Arp, Brp, Wtp, Qp, Kp, Vtp);

    // attention
    dim3 agrid(TT / AT, BX * HH);
    attn_kernel<<<agrid, dim3(512), ATTN_SMEM>>>(Qp, Kp, Vtp, tpad, spad, amask,
                                                 caus, attn_p, Pp);

    // output projection
    if (out_p) {
        gemm_out_kernel<<<dim3(8, 32), 256, GSMEM>>>(Pp, Wtp + 3 * (size_t)EE * EE, bo, out_p);
    }
}

// round 6
// speedup vs baseline: 3.9830x; 1.1617x over previous
#include <cuda_runtime.h>
#include <cuda_bf16.h>
#include <math.h>
#include <cstdint>

// Problem constants
#define BX   4
#define TT   1024
#define SS   1024
#define EE   1024
#define HH   16
#define DH   64

// Scratch (device globals; no allocation allowed)
__device__ float g_Q[BX * HH * TT * DH];   // [B,H,T,D]  tf32, pre-scaled by 1/8
__device__ float g_K[BX * HH * SS * DH];   // [B,H,S,D]  tf32
__device__ float g_Vt[BX * HH * DH * SS];  // [B,H,D,S]  tf32
__device__ float g_P[TT * BX * EE];        // [T,B,E]    tf32
__device__ float g_Wt[4 * EE * EE];        // W^T [N,K]  tf32
__device__ float g_Ar[BX * TT * EE];       // tgt tf32-rounded
__device__ float g_Br[BX * SS * EE];       // src tf32-rounded

// ---------------------------------------------------------------------------
// Helpers
// ---------------------------------------------------------------------------
__device__ __forceinline__ uint32_t smem_u32(const void* p) {
    uint32_t a;
    asm("{ .reg .u64 t; cvta.to.shared.u64 t, %1; cvt.u32.u64 %0, t; }" : "=r"(a) : "l"(p));
    return a;
}
__device__ __forceinline__ float tf32r(float x) {
    uint32_t u;
    asm("cvt.rna.tf32.f32 %0, %1;" : "=r"(u) : "f"(x));
    return __uint_as_float(u);
}
#define SWZ128(off) ((off) ^ (((off) >> 3) & 0x70))

__device__ __forceinline__ void cp16(uint32_t dst, const void* src) {
    asm volatile("cp.async.cg.shared.global [%0], [%1], 16;" :: "r"(dst), "l"(src));
}
#define CP_COMMIT() asm volatile("cp.async.commit_group;" ::: "memory")
#define CP_WAIT1()  asm volatile("cp.async.wait_group 1;" ::: "memory")

__device__ __forceinline__ void ldsm4(uint32_t* r, uint32_t addr) {
    asm volatile("ldmatrix.sync.aligned.m8n8.x4.shared.b16 {%0,%1,%2,%3}, [%4];"
                 : "=r"(r[0]), "=r"(r[1]), "=r"(r[2]), "=r"(r[3]) : "r"(addr));
}
__device__ __forceinline__ void mma_tf32(float* d, const uint32_t* a, uint32_t b0, uint32_t b1) {
    asm volatile("mma.sync.aligned.m16n8k8.row.col.f32.tf32.tf32.f32 "
                 "{%0,%1,%2,%3}, {%4,%5,%6,%7}, {%8,%9}, {%0,%1,%2,%3};"
                 : "+f"(d[0]), "+f"(d[1]), "+f"(d[2]), "+f"(d[3])
                 : "r"(a[0]), "r"(a[1]), "r"(a[2]), "r"(a[3]), "r"(b0), "r"(b1));
}

// ---------------------------------------------------------------------------
// Elementwise tf32 rounding copies (z selects tensor)
// ---------------------------------------------------------------------------
__global__ __launch_bounds__(256)
void round_tf32_kernel(const float* __restrict__ a, const float* __restrict__ b,
                       float* __restrict__ oa, float* __restrict__ ob)
{
    const float* src = blockIdx.z ? b : a;
    float* dst = blockIdx.z ? ob : oa;
    const int n4 = (BX * TT * EE) / 4;
    for (int i = blockIdx.x * 256 + threadIdx.x; i < n4; i += gridDim.x * 256) {
        float4 v = ((const float4*)src)[i];
        v.x = tf32r(v.x); v.y = tf32r(v.y); v.z = tf32r(v.z); v.w = tf32r(v.w);
        ((float4*)dst)[i] = v;
    }
}

// ---------------------------------------------------------------------------
// Weight transpose + tf32 round, 4 weights in one launch (z selects)
// ---------------------------------------------------------------------------
__global__ __launch_bounds__(256)
void transpose_tf32_kernel(const float* __restrict__ W0, const float* __restrict__ W1,
                           const float* __restrict__ W2, const float* __restrict__ W3,
                           float* __restrict__ WtBase)
{
    __shared__ float tile[32][33];
    const int z = blockIdx.z;
    const float* W = (z == 0) ? W0 : (z == 1) ? W1 : (z == 2) ? W2 : W3;
    float* Wt = WtBase + (size_t)z * EE * EE;
    const int k0 = blockIdx.y * 32, n0 = blockIdx.x * 32;
    const int tx = threadIdx.x & 31, ty = threadIdx.x >> 5;
#pragma unroll
    for (int t = 0; t < 4; t++)
        tile[ty + 8 * t][tx] = W[(size_t)(k0 + ty + 8 * t) * EE + n0 + tx];
    __syncthreads();
#pragma unroll
    for (int t = 0; t < 4; t++)
        Wt[(size_t)(n0 + ty + 8 * t) * EE + k0 + tx] = tf32r(tile[tx][ty + 8 * t]);
}

// ---------------------------------------------------------------------------
// tf32 mma.sync GEMM body (unchanged from R5)
// ---------------------------------------------------------------------------
#define GSMEM (3 * 32768 + 1024)

__device__ __forceinline__ void gemm_body(
    const float* __restrict__ A, const float* __restrict__ Bt,
    const float* __restrict__ bias, float* __restrict__ C,
    int mode, float scale, int L)
{
    extern __shared__ char dyn_sm[];
    char* sm = (char*)(((uintptr_t)dyn_sm + 1023) & ~(uintptr_t)1023);
    const uint32_t sb = smem_u32(sm);

    const int tid  = threadIdx.x;
    const int wid  = tid >> 5;
    const int lane = tid & 31;
    const int wm   = wid & 3;
    const int wn   = wid >> 2;
    const int m0 = blockIdx.y * 128;
    const int n0 = blockIdx.x * 128;

    const float* Ap = A  + (size_t)m0 * 1024;
    const float* Bp = Bt + (size_t)n0 * 1024;

    const int lrow  = ((lane >> 3) & 1) * 8 + (lane & 7);
    const int klane = lane >> 4;

    uint32_t aoff[2], asw[2], boff[4], bsw[4];
#pragma unroll
    for (int mt = 0; mt < 2; mt++) {
        int r = wm * 32 + mt * 16 + lrow;
        aoff[mt] = (uint32_t)r * 128;
        asw[mt]  = (uint32_t)(r & 7);
    }
#pragma unroll
    for (int nt = 0; nt < 4; nt++) {
        int r = wn * 64 + nt * 16 + lrow;
        boff[nt] = (uint32_t)r * 128;
        bsw[nt]  = (uint32_t)(r & 7);
    }

    float acc[2][8][4];
#pragma unroll
    for (int mt = 0; mt < 2; mt++)
#pragma unroll
        for (int nt = 0; nt < 8; nt++)
#pragma unroll
            for (int c = 0; c < 4; c++) acc[mt][nt][c] = 0.f;

    auto prefetch = [&](int st, int kt) {
        const int k0 = kt * 32;
        const uint32_t ao = sb + st * 32768;
        const uint32_t bo = ao + 16384;
#pragma unroll
        for (int t = 0; t < 4; t++) {
            int idx = tid + t * 256;
            int r = idx >> 3, c4 = idx & 7;
            uint32_t sw = SWZ128((uint32_t)(r * 128 + c4 * 16));
            cp16(ao + sw, Ap + (size_t)r * 1024 + k0 + c4 * 4);
            cp16(bo + sw, Bp + (size_t)r * 1024 + k0 + c4 * 4);
        }
    };

    prefetch(0, 0); CP_COMMIT();
    prefetch(1, 1); CP_COMMIT();

#pragma unroll 1
    for (int kt = 0; kt < 32; kt++) {
        CP_WAIT1();
        __syncthreads();
        if (kt + 2 < 32) prefetch((kt + 2) % 3, kt + 2);
        CP_COMMIT();

        const uint32_t ab = sb + (kt % 3) * 32768;
        const uint32_t bb = ab + 16384;
#pragma unroll
        for (int k8 = 0; k8 < 4; k8++) {
            const uint32_t kc = (uint32_t)(k8 * 2 + klane);
            uint32_t af[2][4], bf[4][4];
#pragma unroll
            for (int mt = 0; mt < 2; mt++)
                ldsm4(af[mt], ab + aoff[mt] + ((kc ^ asw[mt]) << 4));
#pragma unroll
            for (int nt = 0; nt < 4; nt++)
                ldsm4(bf[nt], bb + boff[nt] + ((kc ^ bsw[nt]) << 4));
#pragma unroll
            for (int mt = 0; mt < 2; mt++)
#pragma unroll
                for (int n8 = 0; n8 < 8; n8++) {
                    int bt = n8 >> 1, sub = n8 & 1;
                    mma_tf32(acc[mt][n8], af[mt], bf[bt][sub], bf[bt][sub + 2]);
                }
        }
    }

    const int rbase = lane >> 2;
    const int cbase = 2 * (lane & 3);
#pragma unroll
    for (int mt = 0; mt < 2; mt++) {
#pragma unroll
        for (int nt = 0; nt < 8; nt++) {
            int n = n0 + wn * 64 + nt * 8 + cbase;
#pragma unroll
            for (int half = 0; half < 2; half++) {
                int m = m0 + wm * 32 + mt * 16 + rbase + half * 8;
                float2 v;
                v.x = acc[mt][nt][half * 2 + 0];
                v.y = acc[mt][nt][half * 2 + 1];
                if (mode == 0) {
                    v.x += bias[n];
                    v.y += bias[n + 1];
                    *(float2*)&C[(size_t)m * 1024 + n] = v;
                } else if (mode == 1) {
                    int b = m / L, l = m % L;
                    size_t o = (((size_t)(b * HH + (n >> 6)) * L + l) * DH) + (n & 63);
                    v.x = tf32r(v.x * scale);
                    v.y = tf32r(v.y * scale);
                    *(float2*)&C[o] = v;
                } else {
                    int b = m / L, s = m % L;
                    size_t o = (((size_t)(b * HH + (n >> 6)) * DH) + (n & 63)) * (size_t)L + s;
                    C[o]     = tf32r(v.x);
                    C[o + L] = tf32r(v.y);
                }
            }
        }
    }
}

__global__ __launch_bounds__(256)
void gemm_qkv_kernel(const float* __restrict__ Atgt, const float* __restrict__ Asrc,
                     const float* __restrict__ Wt,
                     float* __restrict__ Cq, float* __restrict__ Ck, float* __restrict__ Cvt)
{
    const int z = blockIdx.z;
    const float* A = (z == 0) ? Atgt : Asrc;
    const float* W = Wt + (size_t)z * EE * EE;
    float* C = (z == 0) ? Cq : (z == 1) ? Ck : Cvt;
    gemm_body(A, W, nullptr, C, (z == 2) ? 2 : 1, (z == 0) ? 0.125f : 1.0f, (z == 0) ? TT : SS);
}

__global__ __launch_bounds__(256)
void gemm_out_kernel(const float* __restrict__ A, const float* __restrict__ Wt,
                     const float* __restrict__ bias, float* __restrict__ C)
{
    gemm_body(A, Wt, bias, C, 0, 1.0f, TT);
}

// ---------------------------------------------------------------------------
// Fused flash-style tensor-core attention. One block = (b,h) x 64 t-rows,
// 512 threads (16 warps). Per 128-col tile: S-MMA -> exp in regs -> P smem
// (+ unnormalized attn gmem) -> PV-MMA. Final: scale O and attn by 1/rowsum.
// Inputs Q/K/Vt already tf32 (Q pre-scaled by 1/8).
// ---------------------------------------------------------------------------
#define AT2 64
// smem float offsets
#define F_Q    0                    // 64 x 64   (rows 256B swizzled)       4096
#define F_K    4096                 // 2 x (128 x 64)                      16384
#define F_V    20480                // 2 x (64 x 128)  (rows 512B)         16384
#define F_P    36864                // 64 x 128 (rows 512B swizzled)        8192
#define F_SP   45056                // spad row for b                       1024
#define F_PART 46080                // 4 x 64 partial row sums               256
#define F_SUM  46336                // 64 inv sums                            64
#define ATTN2_FLOATS 46656          // + slack -> 186624 B

__global__ __launch_bounds__(512)
void attn_kernel(const float* __restrict__ Q, const float* __restrict__ K,
                 const float* __restrict__ Vt,
                 const float* __restrict__ tpad, const float* __restrict__ spad,
                 const float* __restrict__ amask, const int* __restrict__ causal_p,
                 float* __restrict__ attn_out, float* __restrict__ P)
{
    extern __shared__ float smf[];
    const uint32_t q_b  = smem_u32(smf + F_Q);
    const uint32_t k_b  = smem_u32(smf + F_K);
    const uint32_t v_b  = smem_u32(smf + F_V);
    const uint32_t p_b  = smem_u32(smf + F_P);
    const uint32_t sp_b = smem_u32(smf + F_SP);
    float* s_sp   = smf + F_SP;
    float* s_part = smf + F_PART;
    float* s_sum  = smf + F_SUM;

    const int tid = threadIdx.x;
    const int bh  = blockIdx.y;
    const int b   = bh >> 4;
    const int h   = bh & 15;
    const int t0  = blockIdx.x * AT2;
    const bool causal = (causal_p[0] != 0);

    const size_t qbase  = ((size_t)bh * TT + t0) * DH;
    const size_t kbase  = (size_t)bh * SS * DH;
    const size_t vtbase = (size_t)bh * DH * SS;

    const int lane  = tid & 31;
    const int wid   = tid >> 5;
    const int wm    = wid & 3;    // m16 group (rows wm*16)
    const int wn    = wid >> 2;   // phase1: n32 group; PV: n16 group
    const int lrow  = ((lane >> 3) & 1) * 8 + (lane & 7);
    const int klane = lane >> 4;
    const int rbase = lane >> 2;
    const int cbase = 2 * (lane & 3);

    const int r0 = wm * 16 + rbase;       // this lane's two rows
    const int r1 = r0 + 8;
    const float tm0 = tpad[b * TT + t0 + r0];
    const float tm1 = tpad[b * TT + t0 + r1];

    auto prefetch_k = [&](int it) {
        const uint32_t kb = k_b + (uint32_t)(it & 1) * 32768;
        const int c0 = it * 128;
#pragma unroll
        for (int t = 0; t < 4; t++) {
            int idx = tid + t * 512;
            int r = idx >> 4, c = idx & 15;
            cp16(kb + r * 256 + ((c ^ (r & 7)) << 4),
                 K + kbase + (size_t)(c0 + r) * DH + c * 4);
        }
    };
    auto prefetch_v = [&](int it) {
        const uint32_t vb = v_b + (uint32_t)(it & 1) * 32768;
        const int c0 = it * 128;
#pragma unroll
        for (int t = 0; t < 4; t++) {
            int idx = tid + t * 512;
            int d = idx >> 5, c = idx & 31;
            cp16(vb + d * 512 + ((c ^ (d & 7)) << 4),
                 Vt + vtbase + (size_t)d * SS + c0 + c * 4);
        }
    };

    // prologue: Q + spad + K0 + V0 | K1 + V1
    {
        int idx = tid;            // 1024 chunks of Q, 2 per thread
#pragma unroll
        for (int t = 0; t < 2; t++) {
            int r = idx >> 4, c = idx & 15;
            cp16(q_b + r * 256 + ((c ^ (r & 7)) << 4), Q + qbase + (size_t)r * DH + c * 4);
            idx += 512;
        }
        if (tid < 256) cp16(sp_b + tid * 16, spad + b * SS + tid * 4);
    }
    prefetch_k(0);
    prefetch_v(0);
    CP_COMMIT();
    prefetch_k(1);
    prefetch_v(1);
    CP_COMMIT();

    CP_WAIT1();     // Q, spad, K0, V0 ready
    __syncthreads();

    // preload Q fragments (rows wm*16..+15, k=64)
    const int arow = wm * 16 + lrow;
    uint32_t qf[8][4];
#pragma unroll
    for (int k8 = 0; k8 < 8; k8++) {
        uint32_t kc = (uint32_t)(k8 * 2 + klane);
        ldsm4(qf[k8], q_b + arow * 256 + ((kc ^ (uint32_t)(arow & 7)) << 4));
    }
    const int brow1 = wn * 32 + lrow;   // phase1 B rows (two n16 halves: +0, +16)
    const int arow3 = arow;             // PV A rows (P tile)
    const int brow3 = wn * 16 + lrow;   // PV B rows (V^T tile)

    float rs0 = 0.f, rs1 = 0.f;         // running row sums
    float oacc[2][4];
#pragma unroll
    for (int n8 = 0; n8 < 2; n8++)
#pragma unroll
        for (int c = 0; c < 4; c++) oacc[n8][c] = 0.f;

#pragma unroll 1
    for (int it = 0; it < 8; it++) {
        if (it > 0) {
            CP_WAIT1();
            __syncthreads();
        }
        const int c0 = it * 128;
        const uint32_t kb = k_b + (uint32_t)(it & 1) * 32768;
        const uint32_t vb = v_b + (uint32_t)(it & 1) * 32768;

        // issue mask loads early (latency hidden by S-MMAs)
        float2 am[4][2];
#pragma unroll
        for (int n8 = 0; n8 < 4; n8++) {
            int sc = c0 + wn * 32 + n8 * 8 + cbase;
            am[n8][0] = *(const float2*)&amask[((size_t)b * TT + t0 + r0) * SS + sc];
            am[n8][1] = *(const float2*)&amask[((size_t)b * TT + t0 + r1) * SS + sc];
        }

        // S = Q @ K^T  (warp tile m16 x n32)
        float acc[4][4];
#pragma unroll
        for (int n8 = 0; n8 < 4; n8++)
#pragma unroll
            for (int c = 0; c < 4; c++) acc[n8][c] = 0.f;

#pragma unroll
        for (int k8 = 0; k8 < 8; k8++) {
            uint32_t kc = (uint32_t)(k8 * 2 + klane);
            uint32_t bf0[4], bf1[4];
            ldsm4(bf0, kb + brow1 * 256 + ((kc ^ (uint32_t)(brow1 & 7)) << 4));
            ldsm4(bf1, kb + (brow1 + 16) * 256 + ((kc ^ (uint32_t)((brow1 + 16) & 7)) << 4));
            mma_tf32(acc[0], qf[k8], bf0[0], bf0[2]);
            mma_tf32(acc[1], qf[k8], bf0[1], bf0[3]);
            mma_tf32(acc[2], qf[k8], bf1[0], bf1[2]);
            mma_tf32(acc[3], qf[k8], bf1[1], bf1[3]);
        }

        // exp (no max shift), attn write (unnormalized), P store, row sums
        const int tg0 = t0 + r0, tg1 = t0 + r1;
#pragma unroll
        for (int n8 = 0; n8 < 4; n8++) {
            int scl = wn * 32 + n8 * 8 + cbase;   // local col 0..127
            int sc  = c0 + scl;
            float sp0 = s_sp[sc], sp1 = s_sp[sc + 1];

            float m00 = tm0 * sp0 * am[n8][0].x;
            float m01 = tm0 * sp1 * am[n8][0].y;
            float m10 = tm1 * sp0 * am[n8][1].x;
            float m11 = tm1 * sp1 * am[n8][1].y;
            if (causal) {
                if (sc > tg0)     m00 = 0.f;
                if (sc + 1 > tg0) m01 = 0.f;
                if (sc > tg1)     m10 = 0.f;
                if (sc + 1 > tg1) m11 = 0.f;
            }
            float e00 = __expf(acc[n8][0] + m00);
            float e01 = __expf(acc[n8][1] + m01);
            float e10 = __expf(acc[n8][2] + m10);
            float e11 = __expf(acc[n8][3] + m11);
            rs0 += e00 + e01;
            rs1 += e10 + e11;

            if (attn_out) {
                float2 w0 = {e00, e01}, w1 = {e10, e11};
                *(float2*)&attn_out[((size_t)bh * TT + tg0) * SS + sc] = w0;
                *(float2*)&attn_out[((size_t)bh * TT + tg1) * SS + sc] = w1;
            }
            // P tile store (rows 512B, 16B-chunk swizzle)
            int c4 = scl >> 2, cb = (scl & 3) * 4;
            float2 p0 = {tf32r(e00), tf32r(e01)};
            float2 p1 = {tf32r(e10), tf32r(e11)};
            *(float2*)((char*)smf + F_P * 4 + r0 * 512 + ((c4 ^ (r0 & 7)) << 4) + cb) = p0;
            *(float2*)((char*)smf + F_P * 4 + r1 * 512 + ((c4 ^ (r1 & 7)) << 4) + cb) = p1;
        }
        __syncthreads();   // P complete; K reads done

        // O += P @ V  (warp tile m16 x n16, k=128)
#pragma unroll
        for (int k8 = 0; k8 < 16; k8++) {
            uint32_t kc = (uint32_t)(k8 * 2 + klane);
            uint32_t af[4], bf[4];
            ldsm4(af, p_b + arow3 * 512 + ((kc ^ (uint32_t)(arow3 & 7)) << 4));
            ldsm4(bf, vb + brow3 * 512 + ((kc ^ (uint32_t)(brow3 & 7)) << 4));
            mma_tf32(oacc[0], af, bf[0], bf[2]);
            mma_tf32(oacc[1], af, bf[1], bf[3]);
        }
        __syncthreads();   // PV reads done before buffers refilled

        if (it + 2 < 8) {
            prefetch_k(it + 2);
            prefetch_v(it + 2);
            CP_COMMIT();
        }
    }

    // row-sum reduction: quad shuffle, then cross-warp via smem
    rs0 += __shfl_xor_sync(0xffffffffu, rs0, 1);
    rs0 += __shfl_xor_sync(0xffffffffu, rs0, 2);
    rs1 += __shfl_xor_sync(0xffffffffu, rs1, 1);
    rs1 += __shfl_xor_sync(0xffffffffu, rs1, 2);
    if ((lane & 3) == 0) {
        s_part[wn * 64 + r0] = rs0;
        s_part[wn * 64 + r1] = rs1;
    }
    if (attn_out) asm volatile("membar.cta;" ::: "memory");
    __syncthreads();
    if (tid < 64) {
        float tot = s_part[tid] + s_part[64 + tid] + s_part[128 + tid] + s_part[192 + tid];
        s_sum[tid] = 1.f / tot;
    }
    __syncthreads();

    // scale O by 1/rowsum and write P gmem (tf32)
    {
        float inv0 = s_sum[r0], inv1 = s_sum[r1];
#pragma unroll
        for (int n8 = 0; n8 < 2; n8++) {
            int cc = wn * 16 + n8 * 8 + cbase;
            float2 v0 = {tf32r(oacc[n8][0] * inv0), tf32r(oacc[n8][1] * inv0)};
            float2 v1 = {tf32r(oacc[n8][2] * inv1), tf32r(oacc[n8][3] * inv1)};
            *(float2*)&P[((size_t)(t0 + r0) * BX + b) * EE + h * DH + cc] = v0;
            *(float2*)&P[((size_t)(t0 + r1) * BX + b) * EE + h * DH + cc] = v1;
        }
    }

    // rescale this block's attn rows (unnormalized -> probabilities)
    if (attn_out) {
        const int r = tid >> 3;
        const int l8 = tid & 7;
        const float inv = s_sum[r];
        float* row = attn_out + ((size_t)bh * TT + t0 + r) * SS;
#pragma unroll 8
        for (int i = 0; i < 32; i++) {
            float4 v = *(float4*)&row[l8 * 4 + i * 32];
            v.x *= inv; v.y *= inv; v.z *= inv; v.w *= inv;
            *(float4*)&row[l8 * 4 + i * 32] = v;
        }
    }
}

// ---------------------------------------------------------------------------
// Launch
// ---------------------------------------------------------------------------
extern "C" void kernel_launch(void* const* d_in, const int* in_sizes, int n_in,
                              void* d_out, int out_size)
{
    const float* src   = (const float*)d_in[0];
    const float* tgt   = (const float*)d_in[1];
    const float* spad  = (const float*)d_in[2];
    const float* tpad  = (const float*)d_in[3];
    const float* amask = (const float*)d_in[4];
    const int*   caus  = (const int*)  d_in[5];
    const float* Wq    = (const float*)d_in[6];
    const float* Wk    = (const float*)d_in[7];
    const float* Wv    = (const float*)d_in[8];
    const float* Wo    = (const float*)d_in[9];
    const float* bo    = (const float*)d_in[10];

    const size_t OUT_N  = (size_t)TT * BX * EE;
    const size_t ATTN_N = (size_t)BX * HH * TT * SS;

    float* out_p  = nullptr;
    float* attn_p = nullptr;
    if ((size_t)out_size == OUT_N + ATTN_N) {
        out_p  = (float*)d_out;
        attn_p = (float*)d_out + OUT_N;
    } else if ((size_t)out_size == ATTN_N) {
        attn_p = (float*)d_out;
    } else {
        out_p  = (float*)d_out;
    }

    float *Qp, *Kp, *Vtp, *Pp, *Wtp, *Arp, *Brp;
    cudaGetSymbolAddress((void**)&Qp, g_Q);
    cudaGetSymbolAddress((void**)&Kp, g_K);
    cudaGetSymbolAddress((void**)&Vtp, g_Vt);
    cudaGetSymbolAddress((void**)&Pp, g_P);
    cudaGetSymbolAddress((void**)&Wtp, g_Wt);
    cudaGetSymbolAddress((void**)&Arp, g_Ar);
    cudaGetSymbolAddress((void**)&Brp, g_Br);

    const int ATTN_SMEM = ATTN2_FLOATS * (int)sizeof(float);
    cudaFuncSetAttribute(attn_kernel, cudaFuncAttributeMaxDynamicSharedMemorySize, ATTN_SMEM);
    cudaFuncSetAttribute(gemm_qkv_kernel, cudaFuncAttributeMaxDynamicSharedMemorySize, GSMEM);
    cudaFuncSetAttribute(gemm_out_kernel, cudaFuncAttributeMaxDynamicSharedMemorySize, GSMEM);

    // pre-round inputs + transpose weights
    round_tf32_kernel<<<dim3(512, 1, 2), 256>>>(tgt, src, Arp, Brp);
    transpose_tf32_kernel<<<dim3(32, 32, 4), 256>>>(Wq, Wk, Wv, Wo, Wtp);

    // merged QKV projections
    gemm_qkv_kernel<<<dim3(8, 32, 3), 256, GSMEM>>>(Arp, Brp, Wtp, Qp, Kp, Vtp);

    // fused attention
    dim3 agrid(TT / AT2, BX * HH);   // (16, 64)
    attn_kernel<<<agrid, dim3(512), ATTN_SMEM>>>(Qp, Kp, Vtp, tpad, spad, amask,
                                                 caus, attn_p, Pp);

    // output projection
    if (out_p) {
        gemm_out_kernel<<<dim3(8, 32), 256, GSMEM>>>(Pp, Wtp + 3 * (size_t)EE * EE, bo, out_p);
    }
}